// round 12
// baseline (speedup 1.0000x reference)
#include <cuda_runtime.h>
#include <cuda_fp16.h>
#include <cstdint>

#define Hh 160
#define Ww 160
#define Bn 4
#define HW (Hh*Ww)

// ---------------- scratch (device globals; no allocation allowed) ----------------
// split-fp16 activations: [pix][chunk][hi 32 halfs | lo 32 halfs]  (64 halfs per chunk)
__device__ __align__(16) __half g_lrs[(size_t)Bn*HW*2*64];   // lr, 2 chunks (64ch)
__device__ __align__(16) __half g_hrs[(size_t)Bn*HW*2*64];   // hr, 2 chunks
__device__ __align__(16) __half g_h1s[(size_t)Bn*HW*4*64];   // conv1 out, 4 chunks (128ch)
__device__ __align__(16) __half g_h2s[(size_t)Bn*HW*4*64];   // conv2 out, 4 chunks
__device__ __align__(16) __half g_hrh[(size_t)Bn*HW*64];     // hr NHWC plain fp16 (deform gather)
__device__ float g_off[(size_t)Bn*HW*32];                    // offsets NHWC (18 used, pad 32)
// weights pre-split fp16 hi/lo, pre-swizzled smem image: [kc][oc][128 bytes]
__device__ __align__(16) __half g_BT1[36*128*64];
__device__ __align__(16) __half g_BT2[36*128*64];
__device__ __align__(16) __half g_BTo[36*32*64];
__device__ __align__(16) __half g_BTd[18*64*64];

// ---------------- helpers ----------------
__device__ __forceinline__ uint32_t smem_u32(const void* p) {
    uint32_t a;
    asm("{ .reg .u64 t; cvta.to.shared.u64 t, %1; cvt.u32.u64 %0, t; }" : "=r"(a) : "l"(p));
    return a;
}
__device__ __forceinline__ void ldm4(uint32_t* r, uint32_t addr) {
    asm volatile("ldmatrix.sync.aligned.m8n8.x4.shared.b16 {%0,%1,%2,%3}, [%4];"
                 : "=r"(r[0]), "=r"(r[1]), "=r"(r[2]), "=r"(r[3]) : "r"(addr));
}
// fp32-accumulate MMA (main term)
__device__ __forceinline__ void mma16816(float* c, const uint32_t* a, const uint32_t* b) {
    asm volatile("mma.sync.aligned.m16n8k16.row.col.f32.f16.f16.f32 "
                 "{%0,%1,%2,%3}, {%4,%5,%6,%7}, {%8,%9}, {%0,%1,%2,%3};"
                 : "+f"(c[0]), "+f"(c[1]), "+f"(c[2]), "+f"(c[3])
                 : "r"(a[0]), "r"(a[1]), "r"(a[2]), "r"(a[3]), "r"(b[0]), "r"(b[1]));
}
// fp16-accumulate MMA (correction terms: ~2^-11 magnitude, fp16 acc error negligible)
__device__ __forceinline__ void mma16816h(uint32_t* c, const uint32_t* a, const uint32_t* b) {
    asm volatile("mma.sync.aligned.m16n8k16.row.col.f16.f16.f16.f16 "
                 "{%0,%1}, {%2,%3,%4,%5}, {%6,%7}, {%0,%1};"
                 : "+r"(c[0]), "+r"(c[1])
                 : "r"(a[0]), "r"(a[1]), "r"(a[2]), "r"(a[3]), "r"(b[0]), "r"(b[1]));
}
__device__ __forceinline__ void st128(uint32_t a, uint4 v) {
    asm volatile("st.shared.v4.b32 [%0], {%1,%2,%3,%4};"
                 :: "r"(a), "r"(v.x), "r"(v.y), "r"(v.z), "r"(v.w) : "memory");
}
__device__ __forceinline__ void cp16(uint32_t dst, const void* src, int szbytes) {
    asm volatile("cp.async.cg.shared.global [%0], [%1], 16, %2;"
                 :: "r"(dst), "l"(src), "r"(szbytes) : "memory");
}
#define CP_COMMIT() asm volatile("cp.async.commit_group;" ::: "memory")
__device__ __forceinline__ uint32_t packh2(__half a, __half b) {
    __half2 h = __halves2half2(a, b);
    return *reinterpret_cast<uint32_t*>(&h);
}
__device__ __forceinline__ void split8(float4 u, float4 v, uint4& hi, uint4& lo) {
    float f[8] = {u.x,u.y,u.z,u.w, v.x,v.y,v.z,v.w};
    __half h[8], l[8];
    #pragma unroll
    for (int i = 0; i < 8; i++) {
        h[i] = __float2half_rn(f[i]);
        l[i] = __float2half_rn(f[i] - __half2float(h[i]));
    }
    hi = make_uint4(packh2(h[0],h[1]), packh2(h[2],h[3]), packh2(h[4],h[5]), packh2(h[6],h[7]));
    lo = make_uint4(packh2(l[0],l[1]), packh2(l[2],l[3]), packh2(l[4],l[5]), packh2(l[6],l[7]));
}
// load 16 contiguous fp16 channels -> 8 float2
__device__ __forceinline__ void gath16(const __half* p, float2* f) {
    uint4 q0 = *(const uint4*)p;
    uint4 q1 = *(const uint4*)(p + 8);
    uint32_t u[8] = {q0.x,q0.y,q0.z,q0.w, q1.x,q1.y,q1.z,q1.w};
    #pragma unroll
    for (int i = 0; i < 8; i++) f[i] = __half22float2(*(const __half2*)&u[i]);
}

// ======= 3x3 conv implicit GEMM: 256 threads, 8 warps (WM=4 x WN=2), warp tile 32 x (N/2) =======
// cp.async staging, 3 stages. Main term ah*bh -> fp32 acc; corrections ah*bl + al*bh -> fp16 acc.
template<int N, int OUTK, bool RELU, int NCH, int CPT>
__global__ void __launch_bounds__(256, 1)
mma_conv_cp(const __half* __restrict__ in0h, const __half* __restrict__ in1h,
            const __half* __restrict__ BT, const float* __restrict__ bias,
            float* __restrict__ outf, __half* __restrict__ outh,
            int S0, int S1, int C0CH, int OUT_CS)
{
    constexpr int WM = 4;
    constexpr int MT = 32;          // 128 / WM
    constexpr int NT = N / 2;       // WN = 2
    constexpr int MF = 2;           // MT/16
    constexpr int NF = NT / 8;
    constexpr int ABUF = 128 * 128;
    constexpr int BBUF = N * 128;
    constexpr int STG  = 3;

    extern __shared__ __align__(16) char dsm[];
    const uint32_t smb = (smem_u32(dsm) + 127u) & ~127u;

    const int t = threadIdx.x;
    const int w = t >> 5, lane = t & 31;
    const int wm = w & 3, wn = w >> 2;
    const int xb = blockIdx.x * 32, yb = blockIdx.y * 4, b = blockIdx.z;
    // A staging: thread t stages half a row: row = t>>1, 64B half = t&1
    const int arow_i = t >> 1, ahalf = t & 1;
    const int prow = arow_i >> 5, pcol = arow_i & 31;

    float acc[MF][NF][4];
    uint32_t acc16[MF][NF][2];
    #pragma unroll
    for (int i = 0; i < MF; i++)
        #pragma unroll
        for (int j = 0; j < NF; j++) {
            #pragma unroll
            for (int r = 0; r < 4; r++) acc[i][j][r] = 0.f;
            acc16[i][j][0] = 0u; acc16[i][j][1] = 0u;
        }

    auto stage = [&](int kc) {
        const uint32_t base = smb + (uint32_t)(kc % STG) * (ABUF + BBUF);
        const int tap = kc / CPT, ckl = kc % CPT;
        const int gy = yb + prow + tap/3 - 1;
        const int gx = xb + pcol + tap%3 - 1;
        const bool ok = (gy >= 0 && gy < Hh && gx >= 0 && gx < Ww);
        const size_t pix = (size_t)b*HW + (size_t)(ok ? gy : 0)*Ww + (ok ? gx : 0);
        const __half* src = (ckl < C0CH)
            ? in0h + (pix*S0 + ckl) * 64
            : in1h + (pix*S1 + (ckl - C0CH)) * 64;
        const uint32_t arow = base + (uint32_t)arow_i * 128;
        const int sw = arow_i & 7;
        const int sz = ok ? 16 : 0;
        #pragma unroll
        for (int i = 0; i < 4; i++) {
            const int ch = ahalf*4 + i;
            cp16(arow + (uint32_t)((ch ^ sw) << 4), src + ch*8, sz);
        }
        const __half* bsrc = BT + (size_t)kc*N*64;
        const uint32_t bb = base + ABUF;
        #pragma unroll
        for (int i = 0; i < N/32; i++)
            cp16(bb + (uint32_t)(t + i*256)*16, bsrc + (t + i*256)*8, 16);
        CP_COMMIT();
    };

    auto compute = [&](int kc) {
        const uint32_t Ab = smb + (uint32_t)(kc % STG) * (ABUF + BBUF);
        const uint32_t Bb = Ab + ABUF;
        #pragma unroll
        for (int ks = 0; ks < 2; ks++) {
            uint32_t ah[MF][4], al[MF][4];
            #pragma unroll
            for (int mf = 0; mf < MF; mf++) {
                const int row = wm*MT + mf*16 + (lane & 15);
                const int chh = ks*2 + (lane >> 4);
                const uint32_t rb = Ab + row*128;
                ldm4(ah[mf], rb + (uint32_t)((chh ^ (row&7)) << 4));
                ldm4(al[mf], rb + (uint32_t)(((chh+4) ^ (row&7)) << 4));
            }
            #pragma unroll
            for (int nf2 = 0; nf2 < NF/2; nf2++) {
                uint32_t bh[4], bl[4];
                const int oc  = wn*NT + nf2*16 + (lane & 7) + ((lane >> 4) << 3);
                const int chb = ks*2 + ((lane >> 3) & 1);
                const uint32_t rb = Bb + oc*128;
                ldm4(bh, rb + (uint32_t)((chb ^ (oc&7)) << 4));
                ldm4(bl, rb + (uint32_t)(((chb+4) ^ (oc&7)) << 4));
                // main term: fp32 accumulate
                #pragma unroll
                for (int mf = 0; mf < MF; mf++) mma16816(acc[mf][2*nf2  ], ah[mf], bh+0);
                #pragma unroll
                for (int mf = 0; mf < MF; mf++) mma16816(acc[mf][2*nf2+1], ah[mf], bh+2);
                // correction terms: fp16 accumulate (possibly full-rate vs fp32-acc half-rate)
                #pragma unroll
                for (int mf = 0; mf < MF; mf++) mma16816h(acc16[mf][2*nf2  ], ah[mf], bl+0);
                #pragma unroll
                for (int mf = 0; mf < MF; mf++) mma16816h(acc16[mf][2*nf2+1], ah[mf], bl+2);
                #pragma unroll
                for (int mf = 0; mf < MF; mf++) mma16816h(acc16[mf][2*nf2  ], al[mf], bh+0);
                #pragma unroll
                for (int mf = 0; mf < MF; mf++) mma16816h(acc16[mf][2*nf2+1], al[mf], bh+2);
            }
        }
    };

    stage(0);
    stage(1);
    for (int kc = 0; kc < NCH; kc++) {
        if (kc + 1 < NCH) { asm volatile("cp.async.wait_group 1;" ::: "memory"); }
        else              { asm volatile("cp.async.wait_group 0;" ::: "memory"); }
        __syncthreads();
        compute(kc);
        if (kc + STG - 1 < NCH) stage(kc + STG - 1);
    }

    // ---- epilogue: out = acc32 + float(acc16) ----
    const int lrow = lane >> 2, lcol = (lane & 3) * 2;
    #pragma unroll
    for (int mf = 0; mf < MF; mf++) {
        #pragma unroll
        for (int nf = 0; nf < NF; nf++) {
            const int oc = wn*NT + nf*8 + lcol;
            float bx = 0.f, by = 0.f;
            if (bias != nullptr) { bx = __ldg(bias + oc); by = __ldg(bias + oc + 1); }
            #pragma unroll
            for (int rp = 0; rp < 2; rp++) {
                const int m = wm*MT + mf*16 + lrow + rp*8;
                const int y = yb + (m >> 5), x = xb + (m & 31);
                const float2 corr = __half22float2(*(const __half2*)&acc16[mf][nf][rp]);
                float c0 = acc[mf][nf][rp*2]   + corr.x + bx;
                float c1 = acc[mf][nf][rp*2+1] + corr.y + by;
                if (RELU) { c0 = fmaxf(c0, 0.f); c1 = fmaxf(c1, 0.f); }
                const size_t pix = (size_t)b*HW + (size_t)y*Ww + x;
                if (OUTK == 0) {
                    *(float2*)(outf + pix*OUT_CS + oc) = make_float2(c0, c1);
                } else {
                    __half h0 = __float2half_rn(c0);
                    __half l0 = __float2half_rn(c0 - __half2float(h0));
                    __half h1 = __float2half_rn(c1);
                    __half l1 = __float2half_rn(c1 - __half2float(h1));
                    __half* dst = outh + (pix*(N/32) + (oc >> 5))*64 + (oc & 31);
                    *(__half2*)dst        = __halves2half2(h0, h1);
                    *(__half2*)(dst + 32) = __halves2half2(l0, l1);
                }
            }
        }
    }
}

// ======= fused deformable sampling + 1x1 contraction (K=576 -> 64), fp32 NCHW out =======
// Unchanged from R11 (fp16 hr gather, fp32 interpolation, 3-term fp32-acc split).
__global__ void __launch_bounds__(256)
deform_mma(const __half* __restrict__ hrh, const float* __restrict__ offp,
           const __half* __restrict__ BT, float* __restrict__ outf)
{
    constexpr int N = 64, NCH = 18;
    constexpr int MF = 2, NF = 4;          // WM=4 (MT=32), WN=2 (NT=32)
    constexpr int ABUF = 128 * 128;
    constexpr int BBUF = N * 128;
    constexpr int BV = N / 32;

    extern __shared__ __align__(16) char dsm[];
    const uint32_t smb = (smem_u32(dsm) + 127u) & ~127u;
    const uint32_t Ab0 = smb, Ab1 = smb + ABUF;
    const uint32_t Bb0 = smb + 2*ABUF, Bb1 = smb + 2*ABUF + BBUF;

    const int t = threadIdx.x;
    const int w = t >> 5, lane = t & 31;
    const int wm = w % 4, wn = w / 4;
    const int xb = blockIdx.x * 32, yb = blockIdx.y * 4, b = blockIdx.z;

    float acc[MF][NF][4];
    #pragma unroll
    for (int i = 0; i < MF; i++)
        #pragma unroll
        for (int j = 0; j < NF; j++)
            #pragma unroll
            for (int r = 0; r < 4; r++) acc[i][j][r] = 0.f;

    const int px = t >> 1, half = t & 1;
    const int prow = px >> 5, pcol = px & 31;

    float4 avf[4];
    uint4  bv[BV];
    const __half *cp00 = nullptr, *cp01 = nullptr, *cp10 = nullptr, *cp11 = nullptr;
    float cw00 = 0.f, cw01 = 0.f, cw10 = 0.f, cw11 = 0.f;

    auto load_a = [&](int kc) {
        const int tap = kc >> 1;
        if ((kc & 1) == 0) {
            const int y = yb + prow, x = xb + pcol;
            const size_t pix = (size_t)b*HW + (size_t)y*Ww + x;
            const float dy = offp[pix*32 + 2*tap];
            const float dx = offp[pix*32 + 2*tap + 1];
            const float py  = (float)(y + tap/3 - 1) + dy;
            const float pxx = (float)(x + tap%3 - 1) + dx;
            const float y0f = floorf(py), x0f = floorf(pxx);
            const float wy = py - y0f, wx = pxx - x0f;
            const int yi = (int)y0f, xi = (int)x0f;
            const bool vy0 = (yi   >= 0) && (yi   <= Hh-1);
            const bool vy1 = (yi+1 >= 0) && (yi+1 <= Hh-1);
            const bool vx0 = (xi   >= 0) && (xi   <= Ww-1);
            const bool vx1 = (xi+1 >= 0) && (xi+1 <= Ww-1);
            const int yc0 = min(max(yi,   0), Hh-1);
            const int yc1 = min(max(yi+1, 0), Hh-1);
            const int xc0 = min(max(xi,   0), Ww-1);
            const int xc1 = min(max(xi+1, 0), Ww-1);
            cw00 = (1.f-wy)*(1.f-wx) * ((vy0 && vx0) ? 1.f : 0.f);
            cw01 = (1.f-wy)*wx       * ((vy0 && vx1) ? 1.f : 0.f);
            cw10 = wy*(1.f-wx)       * ((vy1 && vx0) ? 1.f : 0.f);
            cw11 = wy*wx             * ((vy1 && vx1) ? 1.f : 0.f);
            const __half* base = hrh + (size_t)b*HW*64;
            cp00 = base + ((size_t)yc0*Ww + xc0)*64;
            cp01 = base + ((size_t)yc0*Ww + xc1)*64;
            cp10 = base + ((size_t)yc1*Ww + xc0)*64;
            cp11 = base + ((size_t)yc1*Ww + xc1)*64;
        }
        const int cb = ((kc & 1) << 5) + half * 16;
        float2 f00[8], f01[8], f10[8], f11[8];
        gath16(cp00 + cb, f00);
        gath16(cp01 + cb, f01);
        gath16(cp10 + cb, f10);
        gath16(cp11 + cb, f11);
        #pragma unroll
        for (int i = 0; i < 8; i++) {
            const float vx = cw00*f00[i].x + cw01*f01[i].x + cw10*f10[i].x + cw11*f11[i].x;
            const float vy = cw00*f00[i].y + cw01*f01[i].y + cw10*f10[i].y + cw11*f11[i].y;
            if (i & 1) { avf[i>>1].z = vx; avf[i>>1].w = vy; }
            else       { avf[i>>1].x = vx; avf[i>>1].y = vy; }
        }
    };
    auto load_b = [&](int kc) {
        const uint4* src = (const uint4*)(BT + (size_t)kc*N*64);
        #pragma unroll
        for (int i = 0; i < BV; i++) bv[i] = src[t + i*256];
    };
    auto sts_ab = [&](uint32_t Ab, uint32_t Bb) {
        const uint32_t rowb = Ab + px*128;
        const uint32_t sw = px & 7;
        #pragma unroll
        for (int i = 0; i < 2; i++) {
            uint4 hi, lo;
            split8(avf[2*i], avf[2*i+1], hi, lo);
            const int ch = half*2 + i;
            st128(rowb + (uint32_t)((ch ^ sw) << 4), hi);
            st128(rowb + (uint32_t)(((ch+4) ^ sw) << 4), lo);
        }
        #pragma unroll
        for (int i = 0; i < BV; i++) st128(Bb + (t + i*256)*16, bv[i]);
    };
    auto compute = [&](uint32_t Ab, uint32_t Bb) {
        #pragma unroll
        for (int ks = 0; ks < 2; ks++) {
            uint32_t ah[MF][4], al[MF][4];
            #pragma unroll
            for (int mf = 0; mf < MF; mf++) {
                const int row = wm*32 + mf*16 + (lane & 15);
                const int chh = ks*2 + (lane >> 4);
                const uint32_t rb = Ab + row*128;
                ldm4(ah[mf], rb + (uint32_t)((chh ^ (row&7)) << 4));
                ldm4(al[mf], rb + (uint32_t)(((chh+4) ^ (row&7)) << 4));
            }
            #pragma unroll
            for (int nf2 = 0; nf2 < NF/2; nf2++) {
                uint32_t bh[4], bl[4];
                const int oc  = wn*32 + nf2*16 + (lane & 7) + ((lane >> 4) << 3);
                const int chb = ks*2 + ((lane >> 3) & 1);
                const uint32_t rb = Bb + oc*128;
                ldm4(bh, rb + (uint32_t)((chb ^ (oc&7)) << 4));
                ldm4(bl, rb + (uint32_t)(((chb+4) ^ (oc&7)) << 4));
                #pragma unroll
                for (int mf = 0; mf < MF; mf++) mma16816(acc[mf][2*nf2  ], ah[mf], bh+0);
                #pragma unroll
                for (int mf = 0; mf < MF; mf++) mma16816(acc[mf][2*nf2+1], ah[mf], bh+2);
                #pragma unroll
                for (int mf = 0; mf < MF; mf++) mma16816(acc[mf][2*nf2  ], ah[mf], bl+0);
                #pragma unroll
                for (int mf = 0; mf < MF; mf++) mma16816(acc[mf][2*nf2+1], ah[mf], bl+2);
                #pragma unroll
                for (int mf = 0; mf < MF; mf++) mma16816(acc[mf][2*nf2  ], al[mf], bh+0);
                #pragma unroll
                for (int mf = 0; mf < MF; mf++) mma16816(acc[mf][2*nf2+1], al[mf], bh+2);
            }
        }
    };

    load_a(0); load_b(0);
    sts_ab(Ab0, Bb0);
    __syncthreads();

    for (int kc = 0; kc < NCH; kc++) {
        if (kc + 1 < NCH) { load_a(kc+1); load_b(kc+1); }
        compute((kc & 1) ? Ab1 : Ab0, (kc & 1) ? Bb1 : Bb0);
        if (kc + 1 < NCH) {
            sts_ab(((kc+1) & 1) ? Ab1 : Ab0, ((kc+1) & 1) ? Bb1 : Bb0);
            __syncthreads();
        }
    }

    const int lrow = lane >> 2, lcol = (lane & 3) * 2;
    #pragma unroll
    for (int mf = 0; mf < MF; mf++) {
        #pragma unroll
        for (int nf = 0; nf < NF; nf++) {
            const int oc = wn*32 + nf*8 + lcol;
            #pragma unroll
            for (int rp = 0; rp < 2; rp++) {
                const int m = wm*32 + mf*16 + lrow + rp*8;
                const int y = yb + (m >> 5), x = xb + (m & 31);
                const size_t p = (size_t)y*Ww + x;
                outf[((size_t)b*N + oc  )*HW + p] = acc[mf][nf][rp*2];
                outf[((size_t)b*N + oc+1)*HW + p] = acc[mf][nf][rp*2+1];
            }
        }
    }
}

// ---------------- NCHW fp32 -> split fp16 NHWC chunks (+ optional plain fp16 NHWC) ----------------
__global__ void to_nhwc_split(const float* __restrict__ src, __half* __restrict__ dsts,
                              __half* __restrict__ dsth, int C)
{
    __shared__ float tl[32][33];
    const int p0 = blockIdx.x*32, c0 = blockIdx.y*32, b = blockIdx.z;
    const int lx = threadIdx.x & 31, ly = threadIdx.x >> 5;
    #pragma unroll
    for (int i = 0; i < 32; i += 8)
        tl[ly+i][lx] = src[((size_t)b*C + c0 + ly + i)*HW + p0 + lx];
    __syncthreads();
    const int CPT = C / 32;
    #pragma unroll
    for (int i = 0; i < 32; i += 8) {
        const int pix = p0 + ly + i, c = c0 + lx;
        const float v = tl[lx][ly+i];
        __half h = __float2half_rn(v);
        __half l = __float2half_rn(v - __half2float(h));
        __half* d = dsts + (((size_t)b*HW + pix)*CPT + (c >> 5))*64 + (c & 31);
        d[0]  = h;
        d[32] = l;
        if (dsth != nullptr) dsth[((size_t)b*HW + pix)*C + c] = h;
    }
}

// ---------------- weight reformat: split fp16 hi/lo + pre-swizzle smem image ----------------
__global__ void reformat_w_split(const float* __restrict__ w, __half* __restrict__ BT,
                                 int COUT, int NPAD, int CIN, int TOT)
{
    int i = blockIdx.x*blockDim.x + threadIdx.x;
    if (i >= TOT) return;
    int j  = i & 31;
    int oc = (i >> 5) % NPAD;
    int kc = i / (32 * NPAD);
    int kidx = kc*32 + j;
    int tap = kidx / CIN, cin = kidx % CIN;
    float v = (oc < COUT) ? w[((size_t)oc*CIN + cin)*9 + tap] : 0.f;
    __half h = __float2half_rn(v);
    __half l = __float2half_rn(v - __half2float(h));
    int sw = oc & 7;
    size_t rowb = ((size_t)kc*NPAD + oc) * 64;
    int ch = j >> 3, pos = j & 7;
    BT[rowb + (size_t)(((ch    ) ^ sw) << 3) + pos] = h;
    BT[rowb + (size_t)(((ch + 4) ^ sw) << 3) + pos] = l;
}

// ---------------- launch ----------------
extern "C" void kernel_launch(void* const* d_in, const int* in_sizes, int n_in,
                              void* d_out, int out_size)
{
    (void)in_sizes; (void)n_in; (void)out_size;
    const float* lr = (const float*)d_in[0];
    const float* hr = (const float*)d_in[1];
    const float* w1 = (const float*)d_in[2];
    const float* b1 = (const float*)d_in[3];
    const float* w2 = (const float*)d_in[4];
    const float* b2 = (const float*)d_in[5];
    const float* wo = (const float*)d_in[6];
    const float* wd = (const float*)d_in[7];
    float* out = (float*)d_out;

    __half *plrs, *phrs, *ph1s, *ph2s, *phrh, *pBT1, *pBT2, *pBTo, *pBTd;
    float *poff;
    cudaGetSymbolAddress((void**)&plrs, g_lrs);
    cudaGetSymbolAddress((void**)&phrs, g_hrs);
    cudaGetSymbolAddress((void**)&ph1s, g_h1s);
    cudaGetSymbolAddress((void**)&ph2s, g_h2s);
    cudaGetSymbolAddress((void**)&phrh, g_hrh);
    cudaGetSymbolAddress((void**)&poff, g_off);
    cudaGetSymbolAddress((void**)&pBT1, g_BT1);
    cudaGetSymbolAddress((void**)&pBT2, g_BT2);
    cudaGetSymbolAddress((void**)&pBTo, g_BTo);
    cudaGetSymbolAddress((void**)&pBTd, g_BTd);

    const int SZ128 = 3*(16384 + 128*128);   // 98304
    const int SZ32  = 3*(16384 + 32*128);    // 61440
    const int SZD   = 2*16384 + 2*64*128;    // 49152
    cudaFuncSetAttribute(mma_conv_cp<128,1,true ,36,4>,
                         cudaFuncAttributeMaxDynamicSharedMemorySize, SZ128);
    cudaFuncSetAttribute(mma_conv_cp<32 ,0,false,36,4>,
                         cudaFuncAttributeMaxDynamicSharedMemorySize, SZ32);
    cudaFuncSetAttribute(deform_mma,
                         cudaFuncAttributeMaxDynamicSharedMemorySize, SZD);

    // launch order: conv1 at index 3 (ncu profiles launch index 3)
    reformat_w_split<<<(36*128*32+255)/256, 256>>>(w1, pBT1, 128, 128, 128, 36*128*32); // 0
    to_nhwc_split<<<dim3(800,2,Bn), 256>>>(lr, plrs, nullptr, 64);                      // 1
    to_nhwc_split<<<dim3(800,2,Bn), 256>>>(hr, phrs, phrh,    64);                      // 2

    // conv1: concat(lr|hr)(128) -> 128, relu, split-fp16 out   [launch 3: PROFILED]
    mma_conv_cp<128,1,true ,36,4><<<dim3(5,40,Bn), 256, SZ128>>>(
        plrs, phrs, pBT1, b1, nullptr, ph1s, 2, 2, 2, 0);

    reformat_w_split<<<(36*128*32+255)/256, 256>>>(w2, pBT2, 128, 128, 128, 36*128*32); // 4
    reformat_w_split<<<(36*32*32 +255)/256, 256>>>(wo, pBTo, 18,  32,  128, 36*32*32);  // 5
    reformat_w_split<<<(18*64*32 +255)/256, 256>>>(wd, pBTd, 64,  64,  64,  18*64*32);  // 6

    // conv2: 128 -> 128, relu, split-fp16 out
    mma_conv_cp<128,1,true ,36,4><<<dim3(5,40,Bn), 256, SZ128>>>(
        ph1s, ph1s, pBT2, b2, nullptr, ph2s, 4, 4, 4, 0);
    // offset conv: 128 -> 18 (pad 32), fp32 NHWC out
    mma_conv_cp<32 ,0,false,36,4><<<dim3(5,40,Bn), 256, SZ32 >>>(
        ph2s, ph2s, pBTo, nullptr, poff, nullptr, 4, 4, 4, 32);
    // fused deformable sampling + contraction: K=576 -> 64, fp32 NCHW out
    deform_mma<<<dim3(5,40,Bn), 256, SZD>>>(phrh, poff, pBTd, out);
}

// round 13
// speedup vs baseline: 1.3789x; 1.3789x over previous
#include <cuda_runtime.h>
#include <cuda_fp16.h>
#include <cstdint>

#define Hh 160
#define Ww 160
#define Bn 4
#define HW (Hh*Ww)

// ---------------- scratch (device globals; no allocation allowed) ----------------
// split-fp16 activations: [pix][chunk][hi 32 halfs | lo 32 halfs]  (64 halfs per chunk)
__device__ __align__(16) __half g_lrs[(size_t)Bn*HW*2*64];   // lr, 2 chunks (64ch)
__device__ __align__(16) __half g_hrs[(size_t)Bn*HW*2*64];   // hr, 2 chunks
__device__ __align__(16) __half g_h1s[(size_t)Bn*HW*4*64];   // conv1 out, 4 chunks (128ch)
__device__ __align__(16) __half g_h2s[(size_t)Bn*HW*4*64];   // conv2 out, 4 chunks
__device__ __align__(16) __half g_hrh[(size_t)Bn*HW*64];     // hr NHWC plain fp16 (deform gather)
__device__ float g_off[(size_t)Bn*HW*32];                    // offsets NHWC (18 used, pad 32)
// weights pre-split fp16 hi/lo, pre-swizzled smem image: [kc][oc][128 bytes]
__device__ __align__(16) __half g_BT1[36*128*64];
__device__ __align__(16) __half g_BT2[36*128*64];
__device__ __align__(16) __half g_BTo[36*32*64];
__device__ __align__(16) __half g_BTd[18*64*64];

// ---------------- helpers ----------------
__device__ __forceinline__ uint32_t smem_u32(const void* p) {
    uint32_t a;
    asm("{ .reg .u64 t; cvta.to.shared.u64 t, %1; cvt.u32.u64 %0, t; }" : "=r"(a) : "l"(p));
    return a;
}
__device__ __forceinline__ void ldm4(uint32_t* r, uint32_t addr) {
    asm volatile("ldmatrix.sync.aligned.m8n8.x4.shared.b16 {%0,%1,%2,%3}, [%4];"
                 : "=r"(r[0]), "=r"(r[1]), "=r"(r[2]), "=r"(r[3]) : "r"(addr));
}
__device__ __forceinline__ void mma16816(float* c, const uint32_t* a, const uint32_t* b) {
    asm volatile("mma.sync.aligned.m16n8k16.row.col.f32.f16.f16.f32 "
                 "{%0,%1,%2,%3}, {%4,%5,%6,%7}, {%8,%9}, {%0,%1,%2,%3};"
                 : "+f"(c[0]), "+f"(c[1]), "+f"(c[2]), "+f"(c[3])
                 : "r"(a[0]), "r"(a[1]), "r"(a[2]), "r"(a[3]), "r"(b[0]), "r"(b[1]));
}
__device__ __forceinline__ void st128(uint32_t a, uint4 v) {
    asm volatile("st.shared.v4.b32 [%0], {%1,%2,%3,%4};"
                 :: "r"(a), "r"(v.x), "r"(v.y), "r"(v.z), "r"(v.w) : "memory");
}
__device__ __forceinline__ void cp16(uint32_t dst, const void* src, int szbytes) {
    asm volatile("cp.async.cg.shared.global [%0], [%1], 16, %2;"
                 :: "r"(dst), "l"(src), "r"(szbytes) : "memory");
}
#define CP_COMMIT() asm volatile("cp.async.commit_group;" ::: "memory")
__device__ __forceinline__ uint32_t packh2(__half a, __half b) {
    __half2 h = __halves2half2(a, b);
    return *reinterpret_cast<uint32_t*>(&h);
}
__device__ __forceinline__ void split8(float4 u, float4 v, uint4& hi, uint4& lo) {
    float f[8] = {u.x,u.y,u.z,u.w, v.x,v.y,v.z,v.w};
    __half h[8], l[8];
    #pragma unroll
    for (int i = 0; i < 8; i++) {
        h[i] = __float2half_rn(f[i]);
        l[i] = __float2half_rn(f[i] - __half2float(h[i]));
    }
    hi = make_uint4(packh2(h[0],h[1]), packh2(h[2],h[3]), packh2(h[4],h[5]), packh2(h[6],h[7]));
    lo = make_uint4(packh2(l[0],l[1]), packh2(l[2],l[3]), packh2(l[4],l[5]), packh2(l[6],l[7]));
}
// load 16 contiguous fp16 channels -> 8 float2
__device__ __forceinline__ void gath16(const __half* p, float2* f) {
    uint4 q0 = *(const uint4*)p;
    uint4 q1 = *(const uint4*)(p + 8);
    uint32_t u[8] = {q0.x,q0.y,q0.z,q0.w, q1.x,q1.y,q1.z,q1.w};
    #pragma unroll
    for (int i = 0; i < 8; i++) f[i] = __half22float2(*(const __half2*)&u[i]);
}

// ======= 3x3 conv implicit GEMM: 128 threads, 4 warps, warp tile 64 x (N/WN) =======
// cp.async staging, 3 stages, pre-split fp16 NHWC in, 3-term split (ah*bh + ah*bl + al*bh).
// stage(kc+2) is issued BEFORE compute(kc): the barrier above guarantees all warps have
// finished compute(kc-1), so buffer (kc+2)%3 == (kc-1)%3 is free; cp.async gains a full
// compute-duration of extra latency cover. Bit-identical math to R11.
template<int N, int WN, int OUTK, bool RELU, int NCH, int CPT>
__global__ void __launch_bounds__(128, 2)
mma_conv_cp(const __half* __restrict__ in0h, const __half* __restrict__ in1h,
            const __half* __restrict__ BT, const float* __restrict__ bias,
            float* __restrict__ outf, __half* __restrict__ outh,
            int S0, int S1, int C0CH, int OUT_CS)
{
    constexpr int WM = 4 / WN;
    constexpr int MT = 128 / WM;
    constexpr int NT = N / WN;
    constexpr int MF = MT / 16;
    constexpr int NF = NT / 8;
    constexpr int ABUF = 128 * 128;
    constexpr int BBUF = N * 128;
    constexpr int STG  = 3;

    extern __shared__ __align__(16) char dsm[];
    const uint32_t smb = (smem_u32(dsm) + 127u) & ~127u;

    const int t = threadIdx.x;
    const int w = t >> 5, lane = t & 31;
    const int wm = w % WM, wn = w / WM;
    const int xb = blockIdx.x * 32, yb = blockIdx.y * 4, b = blockIdx.z;
    const int prow = t >> 5, pcol = t & 31;

    float acc[MF][NF][4];
    #pragma unroll
    for (int i = 0; i < MF; i++)
        #pragma unroll
        for (int j = 0; j < NF; j++)
            #pragma unroll
            for (int r = 0; r < 4; r++) acc[i][j][r] = 0.f;

    auto stage = [&](int kc) {
        const uint32_t base = smb + (uint32_t)(kc % STG) * (ABUF + BBUF);
        const int tap = kc / CPT, ckl = kc % CPT;
        const int gy = yb + prow + tap/3 - 1;
        const int gx = xb + pcol + tap%3 - 1;
        const bool ok = (gy >= 0 && gy < Hh && gx >= 0 && gx < Ww);
        const size_t pix = (size_t)b*HW + (size_t)(ok ? gy : 0)*Ww + (ok ? gx : 0);
        const __half* src = (ckl < C0CH)
            ? in0h + (pix*S0 + ckl) * 64
            : in1h + (pix*S1 + (ckl - C0CH)) * 64;
        const uint32_t arow = base + (uint32_t)t * 128;
        const int sw = t & 7;
        const int sz = ok ? 16 : 0;
        #pragma unroll
        for (int i = 0; i < 8; i++)
            cp16(arow + (uint32_t)((i ^ sw) << 4), src + i*8, sz);
        const __half* bsrc = BT + (size_t)kc*N*64;
        const uint32_t bb = base + ABUF;
        #pragma unroll
        for (int i = 0; i < N/16; i++)
            cp16(bb + (uint32_t)(t + i*128)*16, bsrc + (t + i*128)*8, 16);
        CP_COMMIT();
    };

    auto compute = [&](int kc) {
        const uint32_t Ab = smb + (uint32_t)(kc % STG) * (ABUF + BBUF);
        const uint32_t Bb = Ab + ABUF;
        #pragma unroll
        for (int ks = 0; ks < 2; ks++) {
            uint32_t ah[MF][4], al[MF][4];
            #pragma unroll
            for (int mf = 0; mf < MF; mf++) {
                const int row = wm*MT + mf*16 + (lane & 15);
                const int chh = ks*2 + (lane >> 4);
                const uint32_t rb = Ab + row*128;
                ldm4(ah[mf], rb + (uint32_t)((chh ^ (row&7)) << 4));
                ldm4(al[mf], rb + (uint32_t)(((chh+4) ^ (row&7)) << 4));
            }
            #pragma unroll
            for (int nf2 = 0; nf2 < NF/2; nf2++) {
                uint32_t bh[4], bl[4];
                const int oc  = wn*NT + nf2*16 + (lane & 7) + ((lane >> 4) << 3);
                const int chb = ks*2 + ((lane >> 3) & 1);
                const uint32_t rb = Bb + oc*128;
                ldm4(bh, rb + (uint32_t)((chb ^ (oc&7)) << 4));
                ldm4(bl, rb + (uint32_t)(((chb+4) ^ (oc&7)) << 4));
                #pragma unroll
                for (int mf = 0; mf < MF; mf++) mma16816(acc[mf][2*nf2  ], ah[mf], bh+0);
                #pragma unroll
                for (int mf = 0; mf < MF; mf++) mma16816(acc[mf][2*nf2+1], ah[mf], bh+2);
                #pragma unroll
                for (int mf = 0; mf < MF; mf++) mma16816(acc[mf][2*nf2  ], ah[mf], bl+0);
                #pragma unroll
                for (int mf = 0; mf < MF; mf++) mma16816(acc[mf][2*nf2+1], ah[mf], bl+2);
                #pragma unroll
                for (int mf = 0; mf < MF; mf++) mma16816(acc[mf][2*nf2  ], al[mf], bh+0);
                #pragma unroll
                for (int mf = 0; mf < MF; mf++) mma16816(acc[mf][2*nf2+1], al[mf], bh+2);
            }
        }
    };

    stage(0);
    stage(1);
    for (int kc = 0; kc < NCH; kc++) {
        if (kc + 1 < NCH) { asm volatile("cp.async.wait_group 1;" ::: "memory"); }
        else              { asm volatile("cp.async.wait_group 0;" ::: "memory"); }
        __syncthreads();
        if (kc + STG - 1 < NCH) stage(kc + STG - 1);   // issue next stage BEFORE compute
        compute(kc);
    }

    // ---- epilogue ----
    const int lrow = lane >> 2, lcol = (lane & 3) * 2;
    #pragma unroll
    for (int mf = 0; mf < MF; mf++) {
        #pragma unroll
        for (int nf = 0; nf < NF; nf++) {
            const int oc = wn*NT + nf*8 + lcol;
            float bx = 0.f, by = 0.f;
            if (bias != nullptr) { bx = __ldg(bias + oc); by = __ldg(bias + oc + 1); }
            #pragma unroll
            for (int rp = 0; rp < 2; rp++) {
                const int m = wm*MT + mf*16 + lrow + rp*8;
                const int y = yb + (m >> 5), x = xb + (m & 31);
                float c0 = acc[mf][nf][rp*2] + bx;
                float c1 = acc[mf][nf][rp*2+1] + by;
                if (RELU) { c0 = fmaxf(c0, 0.f); c1 = fmaxf(c1, 0.f); }
                const size_t pix = (size_t)b*HW + (size_t)y*Ww + x;
                if (OUTK == 0) {
                    *(float2*)(outf + pix*OUT_CS + oc) = make_float2(c0, c1);
                } else {
                    __half h0 = __float2half_rn(c0);
                    __half l0 = __float2half_rn(c0 - __half2float(h0));
                    __half h1 = __float2half_rn(c1);
                    __half l1 = __float2half_rn(c1 - __half2float(h1));
                    __half* dst = outh + (pix*(N/32) + (oc >> 5))*64 + (oc & 31);
                    *(__half2*)dst        = __halves2half2(h0, h1);
                    *(__half2*)(dst + 32) = __halves2half2(l0, l1);
                }
            }
        }
    }
}

// ======= fused deformable sampling + 1x1 contraction (K=576 -> 64), fp32 NCHW out =======
// Unchanged from R11 (fp16 hr gather, fp32 interpolation, 3-term fp32-acc split).
__global__ void __launch_bounds__(256)
deform_mma(const __half* __restrict__ hrh, const float* __restrict__ offp,
           const __half* __restrict__ BT, float* __restrict__ outf)
{
    constexpr int N = 64, NCH = 18;
    constexpr int MF = 2, NF = 4;          // WM=4 (MT=32), WN=2 (NT=32)
    constexpr int ABUF = 128 * 128;
    constexpr int BBUF = N * 128;
    constexpr int BV = N / 32;

    extern __shared__ __align__(16) char dsm[];
    const uint32_t smb = (smem_u32(dsm) + 127u) & ~127u;
    const uint32_t Ab0 = smb, Ab1 = smb + ABUF;
    const uint32_t Bb0 = smb + 2*ABUF, Bb1 = smb + 2*ABUF + BBUF;

    const int t = threadIdx.x;
    const int w = t >> 5, lane = t & 31;
    const int wm = w % 4, wn = w / 4;
    const int xb = blockIdx.x * 32, yb = blockIdx.y * 4, b = blockIdx.z;

    float acc[MF][NF][4];
    #pragma unroll
    for (int i = 0; i < MF; i++)
        #pragma unroll
        for (int j = 0; j < NF; j++)
            #pragma unroll
            for (int r = 0; r < 4; r++) acc[i][j][r] = 0.f;

    const int px = t >> 1, half = t & 1;
    const int prow = px >> 5, pcol = px & 31;

    float4 avf[4];
    uint4  bv[BV];
    const __half *cp00 = nullptr, *cp01 = nullptr, *cp10 = nullptr, *cp11 = nullptr;
    float cw00 = 0.f, cw01 = 0.f, cw10 = 0.f, cw11 = 0.f;

    auto load_a = [&](int kc) {
        const int tap = kc >> 1;
        if ((kc & 1) == 0) {
            const int y = yb + prow, x = xb + pcol;
            const size_t pix = (size_t)b*HW + (size_t)y*Ww + x;
            const float dy = offp[pix*32 + 2*tap];
            const float dx = offp[pix*32 + 2*tap + 1];
            const float py  = (float)(y + tap/3 - 1) + dy;
            const float pxx = (float)(x + tap%3 - 1) + dx;
            const float y0f = floorf(py), x0f = floorf(pxx);
            const float wy = py - y0f, wx = pxx - x0f;
            const int yi = (int)y0f, xi = (int)x0f;
            const bool vy0 = (yi   >= 0) && (yi   <= Hh-1);
            const bool vy1 = (yi+1 >= 0) && (yi+1 <= Hh-1);
            const bool vx0 = (xi   >= 0) && (xi   <= Ww-1);
            const bool vx1 = (xi+1 >= 0) && (xi+1 <= Ww-1);
            const int yc0 = min(max(yi,   0), Hh-1);
            const int yc1 = min(max(yi+1, 0), Hh-1);
            const int xc0 = min(max(xi,   0), Ww-1);
            const int xc1 = min(max(xi+1, 0), Ww-1);
            cw00 = (1.f-wy)*(1.f-wx) * ((vy0 && vx0) ? 1.f : 0.f);
            cw01 = (1.f-wy)*wx       * ((vy0 && vx1) ? 1.f : 0.f);
            cw10 = wy*(1.f-wx)       * ((vy1 && vx0) ? 1.f : 0.f);
            cw11 = wy*wx             * ((vy1 && vx1) ? 1.f : 0.f);
            const __half* base = hrh + (size_t)b*HW*64;
            cp00 = base + ((size_t)yc0*Ww + xc0)*64;
            cp01 = base + ((size_t)yc0*Ww + xc1)*64;
            cp10 = base + ((size_t)yc1*Ww + xc0)*64;
            cp11 = base + ((size_t)yc1*Ww + xc1)*64;
        }
        const int cb = ((kc & 1) << 5) + half * 16;
        float2 f00[8], f01[8], f10[8], f11[8];
        gath16(cp00 + cb, f00);
        gath16(cp01 + cb, f01);
        gath16(cp10 + cb, f10);
        gath16(cp11 + cb, f11);
        #pragma unroll
        for (int i = 0; i < 8; i++) {
            const float vx = cw00*f00[i].x + cw01*f01[i].x + cw10*f10[i].x + cw11*f11[i].x;
            const float vy = cw00*f00[i].y + cw01*f01[i].y + cw10*f10[i].y + cw11*f11[i].y;
            if (i & 1) { avf[i>>1].z = vx; avf[i>>1].w = vy; }
            else       { avf[i>>1].x = vx; avf[i>>1].y = vy; }
        }
    };
    auto load_b = [&](int kc) {
        const uint4* src = (const uint4*)(BT + (size_t)kc*N*64);
        #pragma unroll
        for (int i = 0; i < BV; i++) bv[i] = src[t + i*256];
    };
    auto sts_ab = [&](uint32_t Ab, uint32_t Bb) {
        const uint32_t rowb = Ab + px*128;
        const uint32_t sw = px & 7;
        #pragma unroll
        for (int i = 0; i < 2; i++) {
            uint4 hi, lo;
            split8(avf[2*i], avf[2*i+1], hi, lo);
            const int ch = half*2 + i;
            st128(rowb + (uint32_t)((ch ^ sw) << 4), hi);
            st128(rowb + (uint32_t)(((ch+4) ^ sw) << 4), lo);
        }
        #pragma unroll
        for (int i = 0; i < BV; i++) st128(Bb + (t + i*256)*16, bv[i]);
    };
    auto compute = [&](uint32_t Ab, uint32_t Bb) {
        #pragma unroll
        for (int ks = 0; ks < 2; ks++) {
            uint32_t ah[MF][4], al[MF][4];
            #pragma unroll
            for (int mf = 0; mf < MF; mf++) {
                const int row = wm*32 + mf*16 + (lane & 15);
                const int chh = ks*2 + (lane >> 4);
                const uint32_t rb = Ab + row*128;
                ldm4(ah[mf], rb + (uint32_t)((chh ^ (row&7)) << 4));
                ldm4(al[mf], rb + (uint32_t)(((chh+4) ^ (row&7)) << 4));
            }
            #pragma unroll
            for (int nf2 = 0; nf2 < NF/2; nf2++) {
                uint32_t bh[4], bl[4];
                const int oc  = wn*32 + nf2*16 + (lane & 7) + ((lane >> 4) << 3);
                const int chb = ks*2 + ((lane >> 3) & 1);
                const uint32_t rb = Bb + oc*128;
                ldm4(bh, rb + (uint32_t)((chb ^ (oc&7)) << 4));
                ldm4(bl, rb + (uint32_t)(((chb+4) ^ (oc&7)) << 4));
                #pragma unroll
                for (int mf = 0; mf < MF; mf++) mma16816(acc[mf][2*nf2  ], ah[mf], bh+0);
                #pragma unroll
                for (int mf = 0; mf < MF; mf++) mma16816(acc[mf][2*nf2+1], ah[mf], bh+2);
                #pragma unroll
                for (int mf = 0; mf < MF; mf++) mma16816(acc[mf][2*nf2  ], ah[mf], bl+0);
                #pragma unroll
                for (int mf = 0; mf < MF; mf++) mma16816(acc[mf][2*nf2+1], ah[mf], bl+2);
                #pragma unroll
                for (int mf = 0; mf < MF; mf++) mma16816(acc[mf][2*nf2  ], al[mf], bh+0);
                #pragma unroll
                for (int mf = 0; mf < MF; mf++) mma16816(acc[mf][2*nf2+1], al[mf], bh+2);
            }
        }
    };

    load_a(0); load_b(0);
    sts_ab(Ab0, Bb0);
    __syncthreads();

    for (int kc = 0; kc < NCH; kc++) {
        if (kc + 1 < NCH) { load_a(kc+1); load_b(kc+1); }
        compute((kc & 1) ? Ab1 : Ab0, (kc & 1) ? Bb1 : Bb0);
        if (kc + 1 < NCH) {
            sts_ab(((kc+1) & 1) ? Ab1 : Ab0, ((kc+1) & 1) ? Bb1 : Bb0);
            __syncthreads();
        }
    }

    const int lrow = lane >> 2, lcol = (lane & 3) * 2;
    #pragma unroll
    for (int mf = 0; mf < MF; mf++) {
        #pragma unroll
        for (int nf = 0; nf < NF; nf++) {
            const int oc = wn*32 + nf*8 + lcol;
            #pragma unroll
            for (int rp = 0; rp < 2; rp++) {
                const int m = wm*32 + mf*16 + lrow + rp*8;
                const int y = yb + (m >> 5), x = xb + (m & 31);
                const size_t p = (size_t)y*Ww + x;
                outf[((size_t)b*N + oc  )*HW + p] = acc[mf][nf][rp*2];
                outf[((size_t)b*N + oc+1)*HW + p] = acc[mf][nf][rp*2+1];
            }
        }
    }
}

// ---------------- NCHW fp32 -> split fp16 NHWC chunks, lr+hr in one launch ----------------
// grid.y in [0,4): y<2 -> lr (chunk y), y>=2 -> hr (chunk y-2, also writes plain fp16 copy)
__global__ void to_nhwc_dual(const float* __restrict__ lr, const float* __restrict__ hr,
                             __half* __restrict__ lrs, __half* __restrict__ hrs,
                             __half* __restrict__ hrh)
{
    __shared__ float tl[32][33];
    const int ysel = blockIdx.y;
    const bool is_hr = (ysel >= 2);
    const float* src = is_hr ? hr : lr;
    __half* dsts = is_hr ? hrs : lrs;
    const int p0 = blockIdx.x*32, c0 = (ysel & 1)*32, b = blockIdx.z;
    const int lx = threadIdx.x & 31, ly = threadIdx.x >> 5;
    #pragma unroll
    for (int i = 0; i < 32; i += 8)
        tl[ly+i][lx] = src[((size_t)b*64 + c0 + ly + i)*HW + p0 + lx];
    __syncthreads();
    #pragma unroll
    for (int i = 0; i < 32; i += 8) {
        const int pix = p0 + ly + i, c = c0 + lx;
        const float v = tl[lx][ly+i];
        __half h = __float2half_rn(v);
        __half l = __float2half_rn(v - __half2float(h));
        __half* d = dsts + (((size_t)b*HW + pix)*2 + (c >> 5))*64 + (c & 31);
        d[0]  = h;
        d[32] = l;
        if (is_hr) hrh[((size_t)b*HW + pix)*64 + c] = h;
    }
}

// ---------------- weight reformat: split fp16 hi/lo + pre-swizzle smem image ----------------
__global__ void reformat_w_split(const float* __restrict__ w, __half* __restrict__ BT,
                                 int COUT, int NPAD, int CIN, int TOT)
{
    int i = blockIdx.x*blockDim.x + threadIdx.x;
    if (i >= TOT) return;
    int j  = i & 31;
    int oc = (i >> 5) % NPAD;
    int kc = i / (32 * NPAD);
    int kidx = kc*32 + j;
    int tap = kidx / CIN, cin = kidx % CIN;
    float v = (oc < COUT) ? w[((size_t)oc*CIN + cin)*9 + tap] : 0.f;
    __half h = __float2half_rn(v);
    __half l = __float2half_rn(v - __half2float(h));
    int sw = oc & 7;
    size_t rowb = ((size_t)kc*NPAD + oc) * 64;
    int ch = j >> 3, pos = j & 7;
    BT[rowb + (size_t)(((ch    ) ^ sw) << 3) + pos] = h;
    BT[rowb + (size_t)(((ch + 4) ^ sw) << 3) + pos] = l;
}

// ---------------- launch ----------------
extern "C" void kernel_launch(void* const* d_in, const int* in_sizes, int n_in,
                              void* d_out, int out_size)
{
    (void)in_sizes; (void)n_in; (void)out_size;
    const float* lr = (const float*)d_in[0];
    const float* hr = (const float*)d_in[1];
    const float* w1 = (const float*)d_in[2];
    const float* b1 = (const float*)d_in[3];
    const float* w2 = (const float*)d_in[4];
    const float* b2 = (const float*)d_in[5];
    const float* wo = (const float*)d_in[6];
    const float* wd = (const float*)d_in[7];
    float* out = (float*)d_out;

    __half *plrs, *phrs, *ph1s, *ph2s, *phrh, *pBT1, *pBT2, *pBTo, *pBTd;
    float *poff;
    cudaGetSymbolAddress((void**)&plrs, g_lrs);
    cudaGetSymbolAddress((void**)&phrs, g_hrs);
    cudaGetSymbolAddress((void**)&ph1s, g_h1s);
    cudaGetSymbolAddress((void**)&ph2s, g_h2s);
    cudaGetSymbolAddress((void**)&phrh, g_hrh);
    cudaGetSymbolAddress((void**)&poff, g_off);
    cudaGetSymbolAddress((void**)&pBT1, g_BT1);
    cudaGetSymbolAddress((void**)&pBT2, g_BT2);
    cudaGetSymbolAddress((void**)&pBTo, g_BTo);
    cudaGetSymbolAddress((void**)&pBTd, g_BTd);

    const int SZ128 = 3*(16384 + 128*128);   // 98304
    const int SZ32  = 3*(16384 + 32*128);    // 61440
    const int SZD   = 2*16384 + 2*64*128;    // 49152
    cudaFuncSetAttribute(mma_conv_cp<128,2,1,true ,36,4>,
                         cudaFuncAttributeMaxDynamicSharedMemorySize, SZ128);
    cudaFuncSetAttribute(mma_conv_cp<32 ,1,0,false,36,4>,
                         cudaFuncAttributeMaxDynamicSharedMemorySize, SZ32);
    cudaFuncSetAttribute(deform_mma,
                         cudaFuncAttributeMaxDynamicSharedMemorySize, SZD);

    // launch order: conv1 at index 3 (ncu profiles launch index 3)
    reformat_w_split<<<(36*128*32+255)/256, 256>>>(w1, pBT1, 128, 128, 128, 36*128*32); // 0
    to_nhwc_dual<<<dim3(800,4,Bn), 256>>>(lr, hr, plrs, phrs, phrh);                    // 1
    reformat_w_split<<<(36*128*32+255)/256, 256>>>(w2, pBT2, 128, 128, 128, 36*128*32); // 2

    // conv1: concat(lr|hr)(128) -> 128, relu, split-fp16 out   [launch 3: PROFILED]
    mma_conv_cp<128,2,1,true ,36,4><<<dim3(5,40,Bn), 128, SZ128>>>(
        plrs, phrs, pBT1, b1, nullptr, ph1s, 2, 2, 2, 0);

    reformat_w_split<<<(36*32*32 +255)/256, 256>>>(wo, pBTo, 18,  32,  128, 36*32*32);  // 4
    reformat_w_split<<<(18*64*32 +255)/256, 256>>>(wd, pBTd, 64,  64,  64,  18*64*32);  // 5

    // conv2: 128 -> 128, relu, split-fp16 out
    mma_conv_cp<128,2,1,true ,36,4><<<dim3(5,40,Bn), 128, SZ128>>>(
        ph1s, ph1s, pBT2, b2, nullptr, ph2s, 4, 4, 4, 0);
    // offset conv: 128 -> 18 (pad 32), fp32 NHWC out
    mma_conv_cp<32 ,1,0,false,36,4><<<dim3(5,40,Bn), 128, SZ32 >>>(
        ph2s, ph2s, pBTo, nullptr, poff, nullptr, 4, 4, 4, 32);
    // fused deformable sampling + contraction: K=576 -> 64, fp32 NCHW out
    deform_mma<<<dim3(5,40,Bn), 256, SZD>>>(phrh, poff, pBTd, out);
}

// round 14
// speedup vs baseline: 1.5107x; 1.0956x over previous
#include <cuda_runtime.h>
#include <cuda_fp16.h>
#include <cstdint>

#define Hh 160
#define Ww 160
#define Bn 4
#define HW (Hh*Ww)

// ---------------- scratch (device globals; no allocation allowed) ----------------
// split-fp16 activations: [pix][chunk][hi 32 halfs | lo 32 halfs]  (64 halfs per chunk)
__device__ __align__(16) __half g_lrs[(size_t)Bn*HW*2*64];   // lr, 2 chunks (64ch)
__device__ __align__(16) __half g_hrs[(size_t)Bn*HW*2*64];   // hr, 2 chunks
__device__ __align__(16) __half g_h1s[(size_t)Bn*HW*4*64];   // conv1 out, 4 chunks (128ch)
__device__ __align__(16) __half g_h2s[(size_t)Bn*HW*4*64];   // conv2 out, 4 chunks
__device__ __align__(16) __half g_hrh[(size_t)Bn*HW*64];     // hr NHWC plain fp16 (deform gather)
__device__ float g_off[(size_t)Bn*HW*32];                    // offsets NHWC (18 used, pad 32)
// weights pre-split fp16 hi/lo, pre-swizzled smem image: [kc][oc][128 bytes]
__device__ __align__(16) __half g_BT1[36*128*64];
__device__ __align__(16) __half g_BT2[36*128*64];
__device__ __align__(16) __half g_BTo[36*32*64];
__device__ __align__(16) __half g_BTd[18*64*64];

// ---------------- helpers ----------------
__device__ __forceinline__ uint32_t smem_u32(const void* p) {
    uint32_t a;
    asm("{ .reg .u64 t; cvta.to.shared.u64 t, %1; cvt.u32.u64 %0, t; }" : "=r"(a) : "l"(p));
    return a;
}
__device__ __forceinline__ void ldm4(uint32_t* r, uint32_t addr) {
    asm volatile("ldmatrix.sync.aligned.m8n8.x4.shared.b16 {%0,%1,%2,%3}, [%4];"
                 : "=r"(r[0]), "=r"(r[1]), "=r"(r[2]), "=r"(r[3]) : "r"(addr));
}
__device__ __forceinline__ void mma16816(float* c, const uint32_t* a, const uint32_t* b) {
    asm volatile("mma.sync.aligned.m16n8k16.row.col.f32.f16.f16.f32 "
                 "{%0,%1,%2,%3}, {%4,%5,%6,%7}, {%8,%9}, {%0,%1,%2,%3};"
                 : "+f"(c[0]), "+f"(c[1]), "+f"(c[2]), "+f"(c[3])
                 : "r"(a[0]), "r"(a[1]), "r"(a[2]), "r"(a[3]), "r"(b[0]), "r"(b[1]));
}
__device__ __forceinline__ void st128(uint32_t a, uint4 v) {
    asm volatile("st.shared.v4.b32 [%0], {%1,%2,%3,%4};"
                 :: "r"(a), "r"(v.x), "r"(v.y), "r"(v.z), "r"(v.w) : "memory");
}
__device__ __forceinline__ void cp16(uint32_t dst, const void* src, int szbytes) {
    asm volatile("cp.async.cg.shared.global [%0], [%1], 16, %2;"
                 :: "r"(dst), "l"(src), "r"(szbytes) : "memory");
}
#define CP_COMMIT() asm volatile("cp.async.commit_group;" ::: "memory")
__device__ __forceinline__ uint32_t packh2(__half a, __half b) {
    __half2 h = __halves2half2(a, b);
    return *reinterpret_cast<uint32_t*>(&h);
}
__device__ __forceinline__ void split8(float4 u, float4 v, uint4& hi, uint4& lo) {
    float f[8] = {u.x,u.y,u.z,u.w, v.x,v.y,v.z,v.w};
    __half h[8], l[8];
    #pragma unroll
    for (int i = 0; i < 8; i++) {
        h[i] = __float2half_rn(f[i]);
        l[i] = __float2half_rn(f[i] - __half2float(h[i]));
    }
    hi = make_uint4(packh2(h[0],h[1]), packh2(h[2],h[3]), packh2(h[4],h[5]), packh2(h[6],h[7]));
    lo = make_uint4(packh2(l[0],l[1]), packh2(l[2],l[3]), packh2(l[4],l[5]), packh2(l[6],l[7]));
}
// load 16 contiguous fp16 channels -> 8 float2
__device__ __forceinline__ void gath16(const __half* p, float2* f) {
    uint4 q0 = *(const uint4*)p;
    uint4 q1 = *(const uint4*)(p + 8);
    uint32_t u[8] = {q0.x,q0.y,q0.z,q0.w, q1.x,q1.y,q1.z,q1.w};
    #pragma unroll
    for (int i = 0; i < 8; i++) f[i] = __half22float2(*(const __half2*)&u[i]);
}

// ======= 3x3 conv implicit GEMM: 128 threads, 4 warps, warp tile 64 x (N/WN) =======
// cp.async staging, 3 stages, pre-split fp16 NHWC in, 3-term split (ah*bh + ah*bl + al*bh).
// Loop order: compute(kc) FIRST, then stage(kc+2) — R11 ordering (R13's stage-first
// ordering delayed each chunk's MMA stream by the cp.async issue block and regressed).
template<int N, int WN, int OUTK, bool RELU, int NCH, int CPT>
__global__ void __launch_bounds__(128, 2)
mma_conv_cp(const __half* __restrict__ in0h, const __half* __restrict__ in1h,
            const __half* __restrict__ BT, const float* __restrict__ bias,
            float* __restrict__ outf, __half* __restrict__ outh,
            int S0, int S1, int C0CH, int OUT_CS)
{
    constexpr int WM = 4 / WN;
    constexpr int MT = 128 / WM;
    constexpr int NT = N / WN;
    constexpr int MF = MT / 16;
    constexpr int NF = NT / 8;
    constexpr int ABUF = 128 * 128;
    constexpr int BBUF = N * 128;
    constexpr int STG  = 3;

    extern __shared__ __align__(16) char dsm[];
    const uint32_t smb = (smem_u32(dsm) + 127u) & ~127u;

    const int t = threadIdx.x;
    const int w = t >> 5, lane = t & 31;
    const int wm = w % WM, wn = w / WM;
    const int xb = blockIdx.x * 32, yb = blockIdx.y * 4, b = blockIdx.z;
    const int prow = t >> 5, pcol = t & 31;

    float acc[MF][NF][4];
    #pragma unroll
    for (int i = 0; i < MF; i++)
        #pragma unroll
        for (int j = 0; j < NF; j++)
            #pragma unroll
            for (int r = 0; r < 4; r++) acc[i][j][r] = 0.f;

    auto stage = [&](int kc) {
        const uint32_t base = smb + (uint32_t)(kc % STG) * (ABUF + BBUF);
        const int tap = kc / CPT, ckl = kc % CPT;
        const int gy = yb + prow + tap/3 - 1;
        const int gx = xb + pcol + tap%3 - 1;
        const bool ok = (gy >= 0 && gy < Hh && gx >= 0 && gx < Ww);
        const size_t pix = (size_t)b*HW + (size_t)(ok ? gy : 0)*Ww + (ok ? gx : 0);
        const __half* src = (ckl < C0CH)
            ? in0h + (pix*S0 + ckl) * 64
            : in1h + (pix*S1 + (ckl - C0CH)) * 64;
        const uint32_t arow = base + (uint32_t)t * 128;
        const int sw = t & 7;
        const int sz = ok ? 16 : 0;
        #pragma unroll
        for (int i = 0; i < 8; i++)
            cp16(arow + (uint32_t)((i ^ sw) << 4), src + i*8, sz);
        const __half* bsrc = BT + (size_t)kc*N*64;
        const uint32_t bb = base + ABUF;
        #pragma unroll
        for (int i = 0; i < N/16; i++)
            cp16(bb + (uint32_t)(t + i*128)*16, bsrc + (t + i*128)*8, 16);
        CP_COMMIT();
    };

    auto compute = [&](int kc) {
        const uint32_t Ab = smb + (uint32_t)(kc % STG) * (ABUF + BBUF);
        const uint32_t Bb = Ab + ABUF;
        #pragma unroll
        for (int ks = 0; ks < 2; ks++) {
            uint32_t ah[MF][4], al[MF][4];
            #pragma unroll
            for (int mf = 0; mf < MF; mf++) {
                const int row = wm*MT + mf*16 + (lane & 15);
                const int chh = ks*2 + (lane >> 4);
                const uint32_t rb = Ab + row*128;
                ldm4(ah[mf], rb + (uint32_t)((chh ^ (row&7)) << 4));
                ldm4(al[mf], rb + (uint32_t)(((chh+4) ^ (row&7)) << 4));
            }
            #pragma unroll
            for (int nf2 = 0; nf2 < NF/2; nf2++) {
                uint32_t bh[4], bl[4];
                const int oc  = wn*NT + nf2*16 + (lane & 7) + ((lane >> 4) << 3);
                const int chb = ks*2 + ((lane >> 3) & 1);
                const uint32_t rb = Bb + oc*128;
                ldm4(bh, rb + (uint32_t)((chb ^ (oc&7)) << 4));
                ldm4(bl, rb + (uint32_t)(((chb+4) ^ (oc&7)) << 4));
                #pragma unroll
                for (int mf = 0; mf < MF; mf++) mma16816(acc[mf][2*nf2  ], ah[mf], bh+0);
                #pragma unroll
                for (int mf = 0; mf < MF; mf++) mma16816(acc[mf][2*nf2+1], ah[mf], bh+2);
                #pragma unroll
                for (int mf = 0; mf < MF; mf++) mma16816(acc[mf][2*nf2  ], ah[mf], bl+0);
                #pragma unroll
                for (int mf = 0; mf < MF; mf++) mma16816(acc[mf][2*nf2+1], ah[mf], bl+2);
                #pragma unroll
                for (int mf = 0; mf < MF; mf++) mma16816(acc[mf][2*nf2  ], al[mf], bh+0);
                #pragma unroll
                for (int mf = 0; mf < MF; mf++) mma16816(acc[mf][2*nf2+1], al[mf], bh+2);
            }
        }
    };

    stage(0);
    stage(1);
    for (int kc = 0; kc < NCH; kc++) {
        if (kc + 1 < NCH) { asm volatile("cp.async.wait_group 1;" ::: "memory"); }
        else              { asm volatile("cp.async.wait_group 0;" ::: "memory"); }
        __syncthreads();
        compute(kc);
        if (kc + STG - 1 < NCH) stage(kc + STG - 1);
    }

    // ---- epilogue ----
    const int lrow = lane >> 2, lcol = (lane & 3) * 2;
    #pragma unroll
    for (int mf = 0; mf < MF; mf++) {
        #pragma unroll
        for (int nf = 0; nf < NF; nf++) {
            const int oc = wn*NT + nf*8 + lcol;
            float bx = 0.f, by = 0.f;
            if (bias != nullptr) { bx = __ldg(bias + oc); by = __ldg(bias + oc + 1); }
            #pragma unroll
            for (int rp = 0; rp < 2; rp++) {
                const int m = wm*MT + mf*16 + lrow + rp*8;
                const int y = yb + (m >> 5), x = xb + (m & 31);
                float c0 = acc[mf][nf][rp*2] + bx;
                float c1 = acc[mf][nf][rp*2+1] + by;
                if (RELU) { c0 = fmaxf(c0, 0.f); c1 = fmaxf(c1, 0.f); }
                const size_t pix = (size_t)b*HW + (size_t)y*Ww + x;
                if (OUTK == 0) {
                    *(float2*)(outf + pix*OUT_CS + oc) = make_float2(c0, c1);
                } else {
                    __half h0 = __float2half_rn(c0);
                    __half l0 = __float2half_rn(c0 - __half2float(h0));
                    __half h1 = __float2half_rn(c1);
                    __half l1 = __float2half_rn(c1 - __half2float(h1));
                    __half* dst = outh + (pix*(N/32) + (oc >> 5))*64 + (oc & 31);
                    *(__half2*)dst        = __halves2half2(h0, h1);
                    *(__half2*)(dst + 32) = __halves2half2(l0, l1);
                }
            }
        }
    }
}

// ======= fused deformable sampling + 1x1 contraction (K=576 -> 64), fp32 NCHW out =======
// fp16 hr gather, fp32 interpolation, 3-term fp32-acc split (R11 version, unchanged).
__global__ void __launch_bounds__(256)
deform_mma(const __half* __restrict__ hrh, const float* __restrict__ offp,
           const __half* __restrict__ BT, float* __restrict__ outf)
{
    constexpr int N = 64, NCH = 18;
    constexpr int MF = 2, NF = 4;          // WM=4 (MT=32), WN=2 (NT=32)
    constexpr int ABUF = 128 * 128;
    constexpr int BBUF = N * 128;
    constexpr int BV = N / 32;

    extern __shared__ __align__(16) char dsm[];
    const uint32_t smb = (smem_u32(dsm) + 127u) & ~127u;
    const uint32_t Ab0 = smb, Ab1 = smb + ABUF;
    const uint32_t Bb0 = smb + 2*ABUF, Bb1 = smb + 2*ABUF + BBUF;

    const int t = threadIdx.x;
    const int w = t >> 5, lane = t & 31;
    const int wm = w % 4, wn = w / 4;
    const int xb = blockIdx.x * 32, yb = blockIdx.y * 4, b = blockIdx.z;

    float acc[MF][NF][4];
    #pragma unroll
    for (int i = 0; i < MF; i++)
        #pragma unroll
        for (int j = 0; j < NF; j++)
            #pragma unroll
            for (int r = 0; r < 4; r++) acc[i][j][r] = 0.f;

    const int px = t >> 1, half = t & 1;
    const int prow = px >> 5, pcol = px & 31;

    float4 avf[4];
    uint4  bv[BV];
    const __half *cp00 = nullptr, *cp01 = nullptr, *cp10 = nullptr, *cp11 = nullptr;
    float cw00 = 0.f, cw01 = 0.f, cw10 = 0.f, cw11 = 0.f;

    auto load_a = [&](int kc) {
        const int tap = kc >> 1;
        if ((kc & 1) == 0) {
            const int y = yb + prow, x = xb + pcol;
            const size_t pix = (size_t)b*HW + (size_t)y*Ww + x;
            const float dy = offp[pix*32 + 2*tap];
            const float dx = offp[pix*32 + 2*tap + 1];
            const float py  = (float)(y + tap/3 - 1) + dy;
            const float pxx = (float)(x + tap%3 - 1) + dx;
            const float y0f = floorf(py), x0f = floorf(pxx);
            const float wy = py - y0f, wx = pxx - x0f;
            const int yi = (int)y0f, xi = (int)x0f;
            const bool vy0 = (yi   >= 0) && (yi   <= Hh-1);
            const bool vy1 = (yi+1 >= 0) && (yi+1 <= Hh-1);
            const bool vx0 = (xi   >= 0) && (xi   <= Ww-1);
            const bool vx1 = (xi+1 >= 0) && (xi+1 <= Ww-1);
            const int yc0 = min(max(yi,   0), Hh-1);
            const int yc1 = min(max(yi+1, 0), Hh-1);
            const int xc0 = min(max(xi,   0), Ww-1);
            const int xc1 = min(max(xi+1, 0), Ww-1);
            cw00 = (1.f-wy)*(1.f-wx) * ((vy0 && vx0) ? 1.f : 0.f);
            cw01 = (1.f-wy)*wx       * ((vy0 && vx1) ? 1.f : 0.f);
            cw10 = wy*(1.f-wx)       * ((vy1 && vx0) ? 1.f : 0.f);
            cw11 = wy*wx             * ((vy1 && vx1) ? 1.f : 0.f);
            const __half* base = hrh + (size_t)b*HW*64;
            cp00 = base + ((size_t)yc0*Ww + xc0)*64;
            cp01 = base + ((size_t)yc0*Ww + xc1)*64;
            cp10 = base + ((size_t)yc1*Ww + xc0)*64;
            cp11 = base + ((size_t)yc1*Ww + xc1)*64;
        }
        const int cb = ((kc & 1) << 5) + half * 16;
        float2 f00[8], f01[8], f10[8], f11[8];
        gath16(cp00 + cb, f00);
        gath16(cp01 + cb, f01);
        gath16(cp10 + cb, f10);
        gath16(cp11 + cb, f11);
        #pragma unroll
        for (int i = 0; i < 8; i++) {
            const float vx = cw00*f00[i].x + cw01*f01[i].x + cw10*f10[i].x + cw11*f11[i].x;
            const float vy = cw00*f00[i].y + cw01*f01[i].y + cw10*f10[i].y + cw11*f11[i].y;
            if (i & 1) { avf[i>>1].z = vx; avf[i>>1].w = vy; }
            else       { avf[i>>1].x = vx; avf[i>>1].y = vy; }
        }
    };
    auto load_b = [&](int kc) {
        const uint4* src = (const uint4*)(BT + (size_t)kc*N*64);
        #pragma unroll
        for (int i = 0; i < BV; i++) bv[i] = src[t + i*256];
    };
    auto sts_ab = [&](uint32_t Ab, uint32_t Bb) {
        const uint32_t rowb = Ab + px*128;
        const uint32_t sw = px & 7;
        #pragma unroll
        for (int i = 0; i < 2; i++) {
            uint4 hi, lo;
            split8(avf[2*i], avf[2*i+1], hi, lo);
            const int ch = half*2 + i;
            st128(rowb + (uint32_t)((ch ^ sw) << 4), hi);
            st128(rowb + (uint32_t)(((ch+4) ^ sw) << 4), lo);
        }
        #pragma unroll
        for (int i = 0; i < BV; i++) st128(Bb + (t + i*256)*16, bv[i]);
    };
    auto compute = [&](uint32_t Ab, uint32_t Bb) {
        #pragma unroll
        for (int ks = 0; ks < 2; ks++) {
            uint32_t ah[MF][4], al[MF][4];
            #pragma unroll
            for (int mf = 0; mf < MF; mf++) {
                const int row = wm*32 + mf*16 + (lane & 15);
                const int chh = ks*2 + (lane >> 4);
                const uint32_t rb = Ab + row*128;
                ldm4(ah[mf], rb + (uint32_t)((chh ^ (row&7)) << 4));
                ldm4(al[mf], rb + (uint32_t)(((chh+4) ^ (row&7)) << 4));
            }
            #pragma unroll
            for (int nf2 = 0; nf2 < NF/2; nf2++) {
                uint32_t bh[4], bl[4];
                const int oc  = wn*32 + nf2*16 + (lane & 7) + ((lane >> 4) << 3);
                const int chb = ks*2 + ((lane >> 3) & 1);
                const uint32_t rb = Bb + oc*128;
                ldm4(bh, rb + (uint32_t)((chb ^ (oc&7)) << 4));
                ldm4(bl, rb + (uint32_t)(((chb+4) ^ (oc&7)) << 4));
                #pragma unroll
                for (int mf = 0; mf < MF; mf++) mma16816(acc[mf][2*nf2  ], ah[mf], bh+0);
                #pragma unroll
                for (int mf = 0; mf < MF; mf++) mma16816(acc[mf][2*nf2+1], ah[mf], bh+2);
                #pragma unroll
                for (int mf = 0; mf < MF; mf++) mma16816(acc[mf][2*nf2  ], ah[mf], bl+0);
                #pragma unroll
                for (int mf = 0; mf < MF; mf++) mma16816(acc[mf][2*nf2+1], ah[mf], bl+2);
                #pragma unroll
                for (int mf = 0; mf < MF; mf++) mma16816(acc[mf][2*nf2  ], al[mf], bh+0);
                #pragma unroll
                for (int mf = 0; mf < MF; mf++) mma16816(acc[mf][2*nf2+1], al[mf], bh+2);
            }
        }
    };

    load_a(0); load_b(0);
    sts_ab(Ab0, Bb0);
    __syncthreads();

    for (int kc = 0; kc < NCH; kc++) {
        if (kc + 1 < NCH) { load_a(kc+1); load_b(kc+1); }
        compute((kc & 1) ? Ab1 : Ab0, (kc & 1) ? Bb1 : Bb0);
        if (kc + 1 < NCH) {
            sts_ab(((kc+1) & 1) ? Ab1 : Ab0, ((kc+1) & 1) ? Bb1 : Bb0);
            __syncthreads();
        }
    }

    const int lrow = lane >> 2, lcol = (lane & 3) * 2;
    #pragma unroll
    for (int mf = 0; mf < MF; mf++) {
        #pragma unroll
        for (int nf = 0; nf < NF; nf++) {
            const int oc = wn*32 + nf*8 + lcol;
            #pragma unroll
            for (int rp = 0; rp < 2; rp++) {
                const int m = wm*32 + mf*16 + lrow + rp*8;
                const int y = yb + (m >> 5), x = xb + (m & 31);
                const size_t p = (size_t)y*Ww + x;
                outf[((size_t)b*N + oc  )*HW + p] = acc[mf][nf][rp*2];
                outf[((size_t)b*N + oc+1)*HW + p] = acc[mf][nf][rp*2+1];
            }
        }
    }
}

// ---------------- NCHW fp32 -> split fp16 NHWC chunks, lr+hr in one launch ----------------
// grid.y in [0,4): y<2 -> lr (chunk y), y>=2 -> hr (chunk y-2, also writes plain fp16 copy)
__global__ void to_nhwc_dual(const float* __restrict__ lr, const float* __restrict__ hr,
                             __half* __restrict__ lrs, __half* __restrict__ hrs,
                             __half* __restrict__ hrh)
{
    __shared__ float tl[32][33];
    const int ysel = blockIdx.y;
    const bool is_hr = (ysel >= 2);
    const float* src = is_hr ? hr : lr;
    __half* dsts = is_hr ? hrs : lrs;
    const int p0 = blockIdx.x*32, c0 = (ysel & 1)*32, b = blockIdx.z;
    const int lx = threadIdx.x & 31, ly = threadIdx.x >> 5;
    #pragma unroll
    for (int i = 0; i < 32; i += 8)
        tl[ly+i][lx] = src[((size_t)b*64 + c0 + ly + i)*HW + p0 + lx];
    __syncthreads();
    #pragma unroll
    for (int i = 0; i < 32; i += 8) {
        const int pix = p0 + ly + i, c = c0 + lx;
        const float v = tl[lx][ly+i];
        __half h = __float2half_rn(v);
        __half l = __float2half_rn(v - __half2float(h));
        __half* d = dsts + (((size_t)b*HW + pix)*2 + (c >> 5))*64 + (c & 31);
        d[0]  = h;
        d[32] = l;
        if (is_hr) hrh[((size_t)b*HW + pix)*64 + c] = h;
    }
}

// ---------------- weight reformat: split fp16 hi/lo + pre-swizzle smem image ----------------
__global__ void reformat_w_split(const float* __restrict__ w, __half* __restrict__ BT,
                                 int COUT, int NPAD, int CIN, int TOT)
{
    int i = blockIdx.x*blockDim.x + threadIdx.x;
    if (i >= TOT) return;
    int j  = i & 31;
    int oc = (i >> 5) % NPAD;
    int kc = i / (32 * NPAD);
    int kidx = kc*32 + j;
    int tap = kidx / CIN, cin = kidx % CIN;
    float v = (oc < COUT) ? w[((size_t)oc*CIN + cin)*9 + tap] : 0.f;
    __half h = __float2half_rn(v);
    __half l = __float2half_rn(v - __half2float(h));
    int sw = oc & 7;
    size_t rowb = ((size_t)kc*NPAD + oc) * 64;
    int ch = j >> 3, pos = j & 7;
    BT[rowb + (size_t)(((ch    ) ^ sw) << 3) + pos] = h;
    BT[rowb + (size_t)(((ch + 4) ^ sw) << 3) + pos] = l;
}

// ---------------- launch ----------------
extern "C" void kernel_launch(void* const* d_in, const int* in_sizes, int n_in,
                              void* d_out, int out_size)
{
    (void)in_sizes; (void)n_in; (void)out_size;
    const float* lr = (const float*)d_in[0];
    const float* hr = (const float*)d_in[1];
    const float* w1 = (const float*)d_in[2];
    const float* b1 = (const float*)d_in[3];
    const float* w2 = (const float*)d_in[4];
    const float* b2 = (const float*)d_in[5];
    const float* wo = (const float*)d_in[6];
    const float* wd = (const float*)d_in[7];
    float* out = (float*)d_out;

    __half *plrs, *phrs, *ph1s, *ph2s, *phrh, *pBT1, *pBT2, *pBTo, *pBTd;
    float *poff;
    cudaGetSymbolAddress((void**)&plrs, g_lrs);
    cudaGetSymbolAddress((void**)&phrs, g_hrs);
    cudaGetSymbolAddress((void**)&ph1s, g_h1s);
    cudaGetSymbolAddress((void**)&ph2s, g_h2s);
    cudaGetSymbolAddress((void**)&phrh, g_hrh);
    cudaGetSymbolAddress((void**)&poff, g_off);
    cudaGetSymbolAddress((void**)&pBT1, g_BT1);
    cudaGetSymbolAddress((void**)&pBT2, g_BT2);
    cudaGetSymbolAddress((void**)&pBTo, g_BTo);
    cudaGetSymbolAddress((void**)&pBTd, g_BTd);

    const int SZ128 = 3*(16384 + 128*128);   // 98304
    const int SZ32  = 3*(16384 + 32*128);    // 61440
    const int SZD   = 2*16384 + 2*64*128;    // 49152
    cudaFuncSetAttribute(mma_conv_cp<128,2,1,true ,36,4>,
                         cudaFuncAttributeMaxDynamicSharedMemorySize, SZ128);
    cudaFuncSetAttribute(mma_conv_cp<32 ,1,0,false,36,4>,
                         cudaFuncAttributeMaxDynamicSharedMemorySize, SZ32);
    cudaFuncSetAttribute(deform_mma,
                         cudaFuncAttributeMaxDynamicSharedMemorySize, SZD);

    // launch order: conv1 at index 3 (ncu profiles launch index 3)
    reformat_w_split<<<(36*128*32+255)/256, 256>>>(w1, pBT1, 128, 128, 128, 36*128*32); // 0
    to_nhwc_dual<<<dim3(800,4,Bn), 256>>>(lr, hr, plrs, phrs, phrh);                    // 1
    reformat_w_split<<<(36*128*32+255)/256, 256>>>(w2, pBT2, 128, 128, 128, 36*128*32); // 2

    // conv1: concat(lr|hr)(128) -> 128, relu, split-fp16 out   [launch 3: PROFILED]
    mma_conv_cp<128,2,1,true ,36,4><<<dim3(5,40,Bn), 128, SZ128>>>(
        plrs, phrs, pBT1, b1, nullptr, ph1s, 2, 2, 2, 0);

    reformat_w_split<<<(36*32*32 +255)/256, 256>>>(wo, pBTo, 18,  32,  128, 36*32*32);  // 4
    reformat_w_split<<<(18*64*32 +255)/256, 256>>>(wd, pBTd, 64,  64,  64,  18*64*32);  // 5

    // conv2: 128 -> 128, relu, split-fp16 out
    mma_conv_cp<128,2,1,true ,36,4><<<dim3(5,40,Bn), 128, SZ128>>>(
        ph1s, ph1s, pBT2, b2, nullptr, ph2s, 4, 4, 4, 0);
    // offset conv: 128 -> 18 (pad 32), fp32 NHWC out
    mma_conv_cp<32 ,1,0,false,36,4><<<dim3(5,40,Bn), 128, SZ32 >>>(
        ph2s, ph2s, pBTo, nullptr, poff, nullptr, 4, 4, 4, 32);
    // fused deformable sampling + contraction: K=576 -> 64, fp32 NCHW out
    deform_mma<<<dim3(5,40,Bn), 256, SZD>>>(phrh, poff, pBTd, out);
}

// round 15
// speedup vs baseline: 1.9286x; 1.2766x over previous
#include <cuda_runtime.h>
#include <cuda_fp16.h>
#include <cstdint>

#define Hh 160
#define Ww 160
#define Bn 4
#define HW (Hh*Ww)

// ---------------- scratch (device globals; no allocation allowed) ----------------
// split-fp16 activations: [pix][chunk][hi 32 halfs | lo 32 halfs]  (64 halfs per chunk)
__device__ __align__(16) __half g_lrs[(size_t)Bn*HW*2*64];   // lr, 2 chunks (64ch)
__device__ __align__(16) __half g_hrs[(size_t)Bn*HW*2*64];   // hr, 2 chunks
__device__ __align__(16) __half g_h1s[(size_t)Bn*HW*4*64];   // conv1 out, 4 chunks (128ch)
__device__ __align__(16) __half g_h2s[(size_t)Bn*HW*4*64];   // conv2 out, 4 chunks
__device__ __align__(16) __half g_hrh[(size_t)Bn*HW*64];     // hr NHWC plain fp16 (deform gather)
__device__ float g_off[(size_t)Bn*HW*32];                    // offsets NHWC (18 used, pad 32)
// weights pre-split fp16 hi/lo, pre-swizzled smem image: [kc][oc][128 bytes]
__device__ __align__(16) __half g_BT1[36*128*64];
__device__ __align__(16) __half g_BT2[36*128*64];
__device__ __align__(16) __half g_BTo[36*32*64];
__device__ __align__(16) __half g_BTd[18*64*64];

// ---------------- helpers ----------------
__device__ __forceinline__ uint32_t smem_u32(const void* p) {
    uint32_t a;
    asm("{ .reg .u64 t; cvta.to.shared.u64 t, %1; cvt.u32.u64 %0, t; }" : "=r"(a) : "l"(p));
    return a;
}
__device__ __forceinline__ void ldm4(uint32_t* r, uint32_t addr) {
    asm volatile("ldmatrix.sync.aligned.m8n8.x4.shared.b16 {%0,%1,%2,%3}, [%4];"
                 : "=r"(r[0]), "=r"(r[1]), "=r"(r[2]), "=r"(r[3]) : "r"(addr));
}
__device__ __forceinline__ void mma16816(float* c, const uint32_t* a, const uint32_t* b) {
    asm volatile("mma.sync.aligned.m16n8k16.row.col.f32.f16.f16.f32 "
                 "{%0,%1,%2,%3}, {%4,%5,%6,%7}, {%8,%9}, {%0,%1,%2,%3};"
                 : "+f"(c[0]), "+f"(c[1]), "+f"(c[2]), "+f"(c[3])
                 : "r"(a[0]), "r"(a[1]), "r"(a[2]), "r"(a[3]), "r"(b[0]), "r"(b[1]));
}
__device__ __forceinline__ void st128(uint32_t a, uint4 v) {
    asm volatile("st.shared.v4.b32 [%0], {%1,%2,%3,%4};"
                 :: "r"(a), "r"(v.x), "r"(v.y), "r"(v.z), "r"(v.w) : "memory");
}
__device__ __forceinline__ void cp16(uint32_t dst, const void* src, int szbytes) {
    asm volatile("cp.async.cg.shared.global [%0], [%1], 16, %2;"
                 :: "r"(dst), "l"(src), "r"(szbytes) : "memory");
}
#define CP_COMMIT() asm volatile("cp.async.commit_group;" ::: "memory")
__device__ __forceinline__ uint32_t packh2(__half a, __half b) {
    __half2 h = __halves2half2(a, b);
    return *reinterpret_cast<uint32_t*>(&h);
}
__device__ __forceinline__ void split8(float4 u, float4 v, uint4& hi, uint4& lo) {
    float f[8] = {u.x,u.y,u.z,u.w, v.x,v.y,v.z,v.w};
    __half h[8], l[8];
    #pragma unroll
    for (int i = 0; i < 8; i++) {
        h[i] = __float2half_rn(f[i]);
        l[i] = __float2half_rn(f[i] - __half2float(h[i]));
    }
    hi = make_uint4(packh2(h[0],h[1]), packh2(h[2],h[3]), packh2(h[4],h[5]), packh2(h[6],h[7]));
    lo = make_uint4(packh2(l[0],l[1]), packh2(l[2],l[3]), packh2(l[4],l[5]), packh2(l[6],l[7]));
}
// load 16 contiguous fp16 channels -> 8 float2
__device__ __forceinline__ void gath16(const __half* p, float2* f) {
    uint4 q0 = *(const uint4*)p;
    uint4 q1 = *(const uint4*)(p + 8);
    uint32_t u[8] = {q0.x,q0.y,q0.z,q0.w, q1.x,q1.y,q1.z,q1.w};
    #pragma unroll
    for (int i = 0; i < 8; i++) f[i] = __half22float2(*(const __half2*)&u[i]);
}

// ======= 3x3 conv implicit GEMM with HALO-STAGED A =======
// A: 34x6 halo pixel tile staged ONCE per cin-chunk (204 rows x 128B, row stride 144B =>
// ldmatrix A-reads bank-conflict-free WITHOUT xor swizzle; per-tap A address = +T constant,
// using ldmatrix's per-lane row addressing). A double-buffered, staged at tap==1.
// B: per (tap,ci) tile, triple-buffered, pre-swizzled image (unchanged from R14).
// Loop: ci outer, tap inner; weight chunk kcW = tap*CPT + ci.
// Compute structure / warp tiles / MMA order identical to R14 (validated optimum).
template<int N, int WN, int OUTK, bool RELU, int CPT>
__global__ void __launch_bounds__(128, 2)
mma_conv_halo(const __half* __restrict__ in0h, const __half* __restrict__ in1h,
              const __half* __restrict__ BT, const float* __restrict__ bias,
              float* __restrict__ outf, __half* __restrict__ outh,
              int S0, int S1, int C0CH, int OUT_CS)
{
    constexpr int WM = 4 / WN;
    constexpr int MT = 128 / WM;
    constexpr int NT = N / WN;
    constexpr int MF = MT / 16;
    constexpr int NF = NT / 8;
    constexpr int HROWS = 204;            // 6*34 halo pixels
    constexpr int ASTR  = 144;            // bytes per halo row (conflict-free stride)
    constexpr int ABUFH = HROWS * ASTR;   // 29376
    constexpr int BBUF  = N * 128;
    constexpr int NCH   = CPT * 9;

    extern __shared__ __align__(16) char dsm[];
    const uint32_t smb = (smem_u32(dsm) + 127u) & ~127u;
    const uint32_t Bbase = smb + 2*ABUFH;

    const int t = threadIdx.x;
    const int w = t >> 5, lane = t & 31;
    const int wm = w % WM, wn = w / WM;
    const int xb = blockIdx.x * 32, yb = blockIdx.y * 4, b = blockIdx.z;

    float acc[MF][NF][4];
    #pragma unroll
    for (int i = 0; i < MF; i++)
        #pragma unroll
        for (int j = 0; j < NF; j++)
            #pragma unroll
            for (int r = 0; r < 4; r++) acc[i][j][r] = 0.f;

    // per-lane, per-mf halo row-base byte offsets
    int Lb[MF];
    #pragma unroll
    for (int mf = 0; mf < MF; mf++) {
        const int m = wm*MT + mf*16 + (lane & 15);
        Lb[mf] = ((m >> 5)*34 + (m & 31))*ASTR;
    }

    auto stageA = [&](int ci, int buf) {
        const uint32_t Ab = smb + (uint32_t)buf * ABUFH;
        #pragma unroll 4
        for (int e = t; e < HROWS*8; e += 128) {
            const int row = e >> 3, ch = e & 7;
            const int gy = yb + row/34 - 1;
            const int gx = xb + row%34 - 1;
            const bool ok = (gy >= 0 && gy < Hh && gx >= 0 && gx < Ww);
            const size_t pix = (size_t)b*HW + (size_t)(ok ? gy : 0)*Ww + (ok ? gx : 0);
            const __half* src = (ci < C0CH)
                ? in0h + (pix*S0 + ci)*64 + ch*8
                : in1h + (pix*S1 + (ci - C0CH))*64 + ch*8;
            cp16(Ab + (uint32_t)(row*ASTR + ch*16), src, ok ? 16 : 0);
        }
    };

    auto stageB = [&](int it) {
        const int kcW = (it % 9)*CPT + (it / 9);
        const __half* bsrc = BT + (size_t)kcW*N*64;
        const uint32_t bb = Bbase + (uint32_t)(it % 3)*BBUF;
        #pragma unroll
        for (int i = 0; i < N/16; i++)
            cp16(bb + (uint32_t)(t + i*128)*16, bsrc + (t + i*128)*8, 16);
    };

    auto compute = [&](int it) {
        const uint32_t Ab = smb + (uint32_t)((it/9) & 1) * ABUFH;
        const int tap = it % 9;
        const uint32_t Tof = (uint32_t)(((tap/3)*34 + (tap%3))*ASTR);
        const uint32_t Bb = Bbase + (uint32_t)(it % 3)*BBUF;
        #pragma unroll
        for (int ks = 0; ks < 2; ks++) {
            uint32_t ah[MF][4], al[MF][4];
            #pragma unroll
            for (int mf = 0; mf < MF; mf++) {
                const uint32_t ra = Ab + Tof + (uint32_t)Lb[mf]
                                  + (uint32_t)((ks*2 + (lane >> 4)) << 4);
                ldm4(ah[mf], ra);
                ldm4(al[mf], ra + 64);
            }
            #pragma unroll
            for (int nf2 = 0; nf2 < NF/2; nf2++) {
                uint32_t bh[4], bl[4];
                const int oc  = wn*NT + nf2*16 + (lane & 7) + ((lane >> 4) << 3);
                const int chb = ks*2 + ((lane >> 3) & 1);
                const uint32_t rb = Bb + oc*128;
                ldm4(bh, rb + (uint32_t)((chb ^ (oc&7)) << 4));
                ldm4(bl, rb + (uint32_t)(((chb+4) ^ (oc&7)) << 4));
                #pragma unroll
                for (int mf = 0; mf < MF; mf++) mma16816(acc[mf][2*nf2  ], ah[mf], bh+0);
                #pragma unroll
                for (int mf = 0; mf < MF; mf++) mma16816(acc[mf][2*nf2+1], ah[mf], bh+2);
                #pragma unroll
                for (int mf = 0; mf < MF; mf++) mma16816(acc[mf][2*nf2  ], ah[mf], bl+0);
                #pragma unroll
                for (int mf = 0; mf < MF; mf++) mma16816(acc[mf][2*nf2+1], ah[mf], bl+2);
                #pragma unroll
                for (int mf = 0; mf < MF; mf++) mma16816(acc[mf][2*nf2  ], al[mf], bh+0);
                #pragma unroll
                for (int mf = 0; mf < MF; mf++) mma16816(acc[mf][2*nf2+1], al[mf], bh+2);
            }
        }
    };

    // prologue: A(ci=0) + B(it=0) in one group; B(it=1) in a second group
    stageA(0, 0);
    stageB(0);
    CP_COMMIT();
    stageB(1);
    CP_COMMIT();

    for (int it = 0; it < NCH; it++) {
        if (it + 1 < NCH) { asm volatile("cp.async.wait_group 1;" ::: "memory"); }
        else              { asm volatile("cp.async.wait_group 0;" ::: "memory"); }
        __syncthreads();
        compute(it);
        if (it + 2 < NCH) {
            stageB(it + 2);
            const int ci = it / 9;
            if ((it % 9) == 1 && ci + 1 < CPT) stageA(ci + 1, (ci + 1) & 1);
            CP_COMMIT();
        }
    }

    // ---- epilogue (identical to R14) ----
    const int lrow = lane >> 2, lcol = (lane & 3) * 2;
    #pragma unroll
    for (int mf = 0; mf < MF; mf++) {
        #pragma unroll
        for (int nf = 0; nf < NF; nf++) {
            const int oc = wn*NT + nf*8 + lcol;
            float bx = 0.f, by = 0.f;
            if (bias != nullptr) { bx = __ldg(bias + oc); by = __ldg(bias + oc + 1); }
            #pragma unroll
            for (int rp = 0; rp < 2; rp++) {
                const int m = wm*MT + mf*16 + lrow + rp*8;
                const int y = yb + (m >> 5), x = xb + (m & 31);
                float c0 = acc[mf][nf][rp*2] + bx;
                float c1 = acc[mf][nf][rp*2+1] + by;
                if (RELU) { c0 = fmaxf(c0, 0.f); c1 = fmaxf(c1, 0.f); }
                const size_t pix = (size_t)b*HW + (size_t)y*Ww + x;
                if (OUTK == 0) {
                    *(float2*)(outf + pix*OUT_CS + oc) = make_float2(c0, c1);
                } else {
                    __half h0 = __float2half_rn(c0);
                    __half l0 = __float2half_rn(c0 - __half2float(h0));
                    __half h1 = __float2half_rn(c1);
                    __half l1 = __float2half_rn(c1 - __half2float(h1));
                    __half* dst = outh + (pix*(N/32) + (oc >> 5))*64 + (oc & 31);
                    *(__half2*)dst        = __halves2half2(h0, h1);
                    *(__half2*)(dst + 32) = __halves2half2(l0, l1);
                }
            }
        }
    }
}

// ======= fused deformable sampling + 1x1 contraction (K=576 -> 64), fp32 NCHW out =======
// fp16 hr gather, fp32 interpolation, 3-term fp32-acc split (R11/R14 version, unchanged).
__global__ void __launch_bounds__(256)
deform_mma(const __half* __restrict__ hrh, const float* __restrict__ offp,
           const __half* __restrict__ BT, float* __restrict__ outf)
{
    constexpr int N = 64, NCH = 18;
    constexpr int MF = 2, NF = 4;          // WM=4 (MT=32), WN=2 (NT=32)
    constexpr int ABUF = 128 * 128;
    constexpr int BBUF = N * 128;
    constexpr int BV = N / 32;

    extern __shared__ __align__(16) char dsm[];
    const uint32_t smb = (smem_u32(dsm) + 127u) & ~127u;
    const uint32_t Ab0 = smb, Ab1 = smb + ABUF;
    const uint32_t Bb0 = smb + 2*ABUF, Bb1 = smb + 2*ABUF + BBUF;

    const int t = threadIdx.x;
    const int w = t >> 5, lane = t & 31;
    const int wm = w % 4, wn = w / 4;
    const int xb = blockIdx.x * 32, yb = blockIdx.y * 4, b = blockIdx.z;

    float acc[MF][NF][4];
    #pragma unroll
    for (int i = 0; i < MF; i++)
        #pragma unroll
        for (int j = 0; j < NF; j++)
            #pragma unroll
            for (int r = 0; r < 4; r++) acc[i][j][r] = 0.f;

    const int px = t >> 1, half = t & 1;
    const int prow = px >> 5, pcol = px & 31;

    float4 avf[4];
    uint4  bv[BV];
    const __half *cp00 = nullptr, *cp01 = nullptr, *cp10 = nullptr, *cp11 = nullptr;
    float cw00 = 0.f, cw01 = 0.f, cw10 = 0.f, cw11 = 0.f;

    auto load_a = [&](int kc) {
        const int tap = kc >> 1;
        if ((kc & 1) == 0) {
            const int y = yb + prow, x = xb + pcol;
            const size_t pix = (size_t)b*HW + (size_t)y*Ww + x;
            const float dy = offp[pix*32 + 2*tap];
            const float dx = offp[pix*32 + 2*tap + 1];
            const float py  = (float)(y + tap/3 - 1) + dy;
            const float pxx = (float)(x + tap%3 - 1) + dx;
            const float y0f = floorf(py), x0f = floorf(pxx);
            const float wy = py - y0f, wx = pxx - x0f;
            const int yi = (int)y0f, xi = (int)x0f;
            const bool vy0 = (yi   >= 0) && (yi   <= Hh-1);
            const bool vy1 = (yi+1 >= 0) && (yi+1 <= Hh-1);
            const bool vx0 = (xi   >= 0) && (xi   <= Ww-1);
            const bool vx1 = (xi+1 >= 0) && (xi+1 <= Ww-1);
            const int yc0 = min(max(yi,   0), Hh-1);
            const int yc1 = min(max(yi+1, 0), Hh-1);
            const int xc0 = min(max(xi,   0), Ww-1);
            const int xc1 = min(max(xi+1, 0), Ww-1);
            cw00 = (1.f-wy)*(1.f-wx) * ((vy0 && vx0) ? 1.f : 0.f);
            cw01 = (1.f-wy)*wx       * ((vy0 && vx1) ? 1.f : 0.f);
            cw10 = wy*(1.f-wx)       * ((vy1 && vx0) ? 1.f : 0.f);
            cw11 = wy*wx             * ((vy1 && vx1) ? 1.f : 0.f);
            const __half* base = hrh + (size_t)b*HW*64;
            cp00 = base + ((size_t)yc0*Ww + xc0)*64;
            cp01 = base + ((size_t)yc0*Ww + xc1)*64;
            cp10 = base + ((size_t)yc1*Ww + xc0)*64;
            cp11 = base + ((size_t)yc1*Ww + xc1)*64;
        }
        const int cb = ((kc & 1) << 5) + half * 16;
        float2 f00[8], f01[8], f10[8], f11[8];
        gath16(cp00 + cb, f00);
        gath16(cp01 + cb, f01);
        gath16(cp10 + cb, f10);
        gath16(cp11 + cb, f11);
        #pragma unroll
        for (int i = 0; i < 8; i++) {
            const float vx = cw00*f00[i].x + cw01*f01[i].x + cw10*f10[i].x + cw11*f11[i].x;
            const float vy = cw00*f00[i].y + cw01*f01[i].y + cw10*f10[i].y + cw11*f11[i].y;
            if (i & 1) { avf[i>>1].z = vx; avf[i>>1].w = vy; }
            else       { avf[i>>1].x = vx; avf[i>>1].y = vy; }
        }
    };
    auto load_b = [&](int kc) {
        const uint4* src = (const uint4*)(BT + (size_t)kc*N*64);
        #pragma unroll
        for (int i = 0; i < BV; i++) bv[i] = src[t + i*256];
    };
    auto sts_ab = [&](uint32_t Ab, uint32_t Bb) {
        const uint32_t rowb = Ab + px*128;
        const uint32_t sw = px & 7;
        #pragma unroll
        for (int i = 0; i < 2; i++) {
            uint4 hi, lo;
            split8(avf[2*i], avf[2*i+1], hi, lo);
            const int ch = half*2 + i;
            st128(rowb + (uint32_t)((ch ^ sw) << 4), hi);
            st128(rowb + (uint32_t)(((ch+4) ^ sw) << 4), lo);
        }
        #pragma unroll
        for (int i = 0; i < BV; i++) st128(Bb + (t + i*256)*16, bv[i]);
    };
    auto compute = [&](uint32_t Ab, uint32_t Bb) {
        #pragma unroll
        for (int ks = 0; ks < 2; ks++) {
            uint32_t ah[MF][4], al[MF][4];
            #pragma unroll
            for (int mf = 0; mf < MF; mf++) {
                const int row = wm*32 + mf*16 + (lane & 15);
                const int chh = ks*2 + (lane >> 4);
                const uint32_t rb = Ab + row*128;
                ldm4(ah[mf], rb + (uint32_t)((chh ^ (row&7)) << 4));
                ldm4(al[mf], rb + (uint32_t)(((chh+4) ^ (row&7)) << 4));
            }
            #pragma unroll
            for (int nf2 = 0; nf2 < NF/2; nf2++) {
                uint32_t bh[4], bl[4];
                const int oc  = wn*32 + nf2*16 + (lane & 7) + ((lane >> 4) << 3);
                const int chb = ks*2 + ((lane >> 3) & 1);
                const uint32_t rb = Bb + oc*128;
                ldm4(bh, rb + (uint32_t)((chb ^ (oc&7)) << 4));
                ldm4(bl, rb + (uint32_t)(((chb+4) ^ (oc&7)) << 4));
                #pragma unroll
                for (int mf = 0; mf < MF; mf++) mma16816(acc[mf][2*nf2  ], ah[mf], bh+0);
                #pragma unroll
                for (int mf = 0; mf < MF; mf++) mma16816(acc[mf][2*nf2+1], ah[mf], bh+2);
                #pragma unroll
                for (int mf = 0; mf < MF; mf++) mma16816(acc[mf][2*nf2  ], ah[mf], bl+0);
                #pragma unroll
                for (int mf = 0; mf < MF; mf++) mma16816(acc[mf][2*nf2+1], ah[mf], bl+2);
                #pragma unroll
                for (int mf = 0; mf < MF; mf++) mma16816(acc[mf][2*nf2  ], al[mf], bh+0);
                #pragma unroll
                for (int mf = 0; mf < MF; mf++) mma16816(acc[mf][2*nf2+1], al[mf], bh+2);
            }
        }
    };

    load_a(0); load_b(0);
    sts_ab(Ab0, Bb0);
    __syncthreads();

    for (int kc = 0; kc < NCH; kc++) {
        if (kc + 1 < NCH) { load_a(kc+1); load_b(kc+1); }
        compute((kc & 1) ? Ab1 : Ab0, (kc & 1) ? Bb1 : Bb0);
        if (kc + 1 < NCH) {
            sts_ab(((kc+1) & 1) ? Ab1 : Ab0, ((kc+1) & 1) ? Bb1 : Bb0);
            __syncthreads();
        }
    }

    const int lrow = lane >> 2, lcol = (lane & 3) * 2;
    #pragma unroll
    for (int mf = 0; mf < MF; mf++) {
        #pragma unroll
        for (int nf = 0; nf < NF; nf++) {
            const int oc = wn*32 + nf*8 + lcol;
            #pragma unroll
            for (int rp = 0; rp < 2; rp++) {
                const int m = wm*32 + mf*16 + lrow + rp*8;
                const int y = yb + (m >> 5), x = xb + (m & 31);
                const size_t p = (size_t)y*Ww + x;
                outf[((size_t)b*N + oc  )*HW + p] = acc[mf][nf][rp*2];
                outf[((size_t)b*N + oc+1)*HW + p] = acc[mf][nf][rp*2+1];
            }
        }
    }
}

// ---------------- NCHW fp32 -> split fp16 NHWC chunks, lr+hr in one launch ----------------
__global__ void to_nhwc_dual(const float* __restrict__ lr, const float* __restrict__ hr,
                             __half* __restrict__ lrs, __half* __restrict__ hrs,
                             __half* __restrict__ hrh)
{
    __shared__ float tl[32][33];
    const int ysel = blockIdx.y;
    const bool is_hr = (ysel >= 2);
    const float* src = is_hr ? hr : lr;
    __half* dsts = is_hr ? hrs : lrs;
    const int p0 = blockIdx.x*32, c0 = (ysel & 1)*32, b = blockIdx.z;
    const int lx = threadIdx.x & 31, ly = threadIdx.x >> 5;
    #pragma unroll
    for (int i = 0; i < 32; i += 8)
        tl[ly+i][lx] = src[((size_t)b*64 + c0 + ly + i)*HW + p0 + lx];
    __syncthreads();
    #pragma unroll
    for (int i = 0; i < 32; i += 8) {
        const int pix = p0 + ly + i, c = c0 + lx;
        const float v = tl[lx][ly+i];
        __half h = __float2half_rn(v);
        __half l = __float2half_rn(v - __half2float(h));
        __half* d = dsts + (((size_t)b*HW + pix)*2 + (c >> 5))*64 + (c & 31);
        d[0]  = h;
        d[32] = l;
        if (is_hr) hrh[((size_t)b*HW + pix)*64 + c] = h;
    }
}

// ---------------- weight reformat: split fp16 hi/lo + pre-swizzle smem image ----------------
__global__ void reformat_w_split(const float* __restrict__ w, __half* __restrict__ BT,
                                 int COUT, int NPAD, int CIN, int TOT)
{
    int i = blockIdx.x*blockDim.x + threadIdx.x;
    if (i >= TOT) return;
    int j  = i & 31;
    int oc = (i >> 5) % NPAD;
    int kc = i / (32 * NPAD);
    int kidx = kc*32 + j;
    int tap = kidx / CIN, cin = kidx % CIN;
    float v = (oc < COUT) ? w[((size_t)oc*CIN + cin)*9 + tap] : 0.f;
    __half h = __float2half_rn(v);
    __half l = __float2half_rn(v - __half2float(h));
    int sw = oc & 7;
    size_t rowb = ((size_t)kc*NPAD + oc) * 64;
    int ch = j >> 3, pos = j & 7;
    BT[rowb + (size_t)(((ch    ) ^ sw) << 3) + pos] = h;
    BT[rowb + (size_t)(((ch + 4) ^ sw) << 3) + pos] = l;
}

// ---------------- launch ----------------
extern "C" void kernel_launch(void* const* d_in, const int* in_sizes, int n_in,
                              void* d_out, int out_size)
{
    (void)in_sizes; (void)n_in; (void)out_size;
    const float* lr = (const float*)d_in[0];
    const float* hr = (const float*)d_in[1];
    const float* w1 = (const float*)d_in[2];
    const float* b1 = (const float*)d_in[3];
    const float* w2 = (const float*)d_in[4];
    const float* b2 = (const float*)d_in[5];
    const float* wo = (const float*)d_in[6];
    const float* wd = (const float*)d_in[7];
    float* out = (float*)d_out;

    __half *plrs, *phrs, *ph1s, *ph2s, *phrh, *pBT1, *pBT2, *pBTo, *pBTd;
    float *poff;
    cudaGetSymbolAddress((void**)&plrs, g_lrs);
    cudaGetSymbolAddress((void**)&phrs, g_hrs);
    cudaGetSymbolAddress((void**)&ph1s, g_h1s);
    cudaGetSymbolAddress((void**)&ph2s, g_h2s);
    cudaGetSymbolAddress((void**)&phrh, g_hrh);
    cudaGetSymbolAddress((void**)&poff, g_off);
    cudaGetSymbolAddress((void**)&pBT1, g_BT1);
    cudaGetSymbolAddress((void**)&pBT2, g_BT2);
    cudaGetSymbolAddress((void**)&pBTo, g_BTo);
    cudaGetSymbolAddress((void**)&pBTd, g_BTd);

    const int SZ128 = 2*29376 + 3*16384 + 128;   // 108160
    const int SZ32  = 2*29376 + 3*4096  + 128;   //  71168
    const int SZD   = 2*16384 + 2*64*128;        //  49152
    cudaFuncSetAttribute(mma_conv_halo<128,2,1,true ,4>,
                         cudaFuncAttributeMaxDynamicSharedMemorySize, SZ128);
    cudaFuncSetAttribute(mma_conv_halo<32 ,1,0,false,4>,
                         cudaFuncAttributeMaxDynamicSharedMemorySize, SZ32);
    cudaFuncSetAttribute(deform_mma,
                         cudaFuncAttributeMaxDynamicSharedMemorySize, SZD);

    // launch order: conv1 at index 3 (ncu profiles launch index 3)
    reformat_w_split<<<(36*128*32+255)/256, 256>>>(w1, pBT1, 128, 128, 128, 36*128*32); // 0
    to_nhwc_dual<<<dim3(800,4,Bn), 256>>>(lr, hr, plrs, phrs, phrh);                    // 1
    reformat_w_split<<<(36*128*32+255)/256, 256>>>(w2, pBT2, 128, 128, 128, 36*128*32); // 2

    // conv1: concat(lr|hr)(128) -> 128, relu, split-fp16 out   [launch 3: PROFILED]
    mma_conv_halo<128,2,1,true ,4><<<dim3(5,40,Bn), 128, SZ128>>>(
        plrs, phrs, pBT1, b1, nullptr, ph1s, 2, 2, 2, 0);

    reformat_w_split<<<(36*32*32 +255)/256, 256>>>(wo, pBTo, 18,  32,  128, 36*32*32);  // 4
    reformat_w_split<<<(18*64*32 +255)/256, 256>>>(wd, pBTd, 64,  64,  64,  18*64*32);  // 5

    // conv2: 128 -> 128, relu, split-fp16 out
    mma_conv_halo<128,2,1,true ,4><<<dim3(5,40,Bn), 128, SZ128>>>(
        ph1s, ph1s, pBT2, b2, nullptr, ph2s, 4, 4, 4, 0);
    // offset conv: 128 -> 18 (pad 32), fp32 NHWC out
    mma_conv_halo<32 ,1,0,false,4><<<dim3(5,40,Bn), 128, SZ32 >>>(
        ph2s, ph2s, pBTo, nullptr, poff, nullptr, 4, 4, 4, 32);
    // fused deformable sampling + contraction: K=576 -> 64, fp32 NCHW out
    deform_mma<<<dim3(5,40,Bn), 256, SZD>>>(phrh, poff, pBTd, out);
}

// round 16
// speedup vs baseline: 1.9799x; 1.0266x over previous
#include <cuda_runtime.h>
#include <cuda_fp16.h>
#include <cstdint>

#define Hh 160
#define Ww 160
#define Bn 4
#define HW (Hh*Ww)

// ---------------- scratch (device globals; no allocation allowed) ----------------
// split-fp16 activations: [pix][chunk][hi 32 halfs | lo 32 halfs]  (64 halfs per chunk)
__device__ __align__(16) __half g_lrs[(size_t)Bn*HW*2*64];   // lr, 2 chunks (64ch)
__device__ __align__(16) __half g_hrs[(size_t)Bn*HW*2*64];   // hr, 2 chunks
__device__ __align__(16) __half g_h1s[(size_t)Bn*HW*4*64];   // conv1 out, 4 chunks (128ch)
__device__ __align__(16) __half g_h2s[(size_t)Bn*HW*4*64];   // conv2 out, 4 chunks
__device__ __align__(16) __half g_hrh[(size_t)Bn*HW*64];     // hr NHWC plain fp16 (deform gather)
__device__ float g_off[(size_t)Bn*HW*32];                    // offsets NHWC (18 used, pad 32)
// weights pre-split fp16 hi/lo, pre-swizzled smem image: [kc][oc][128 bytes]
__device__ __align__(16) __half g_BT1[36*128*64];
__device__ __align__(16) __half g_BT2[36*128*64];
__device__ __align__(16) __half g_BTo[36*32*64];
__device__ __align__(16) __half g_BTd[18*64*64];

// ---------------- helpers ----------------
__device__ __forceinline__ uint32_t smem_u32(const void* p) {
    uint32_t a;
    asm("{ .reg .u64 t; cvta.to.shared.u64 t, %1; cvt.u32.u64 %0, t; }" : "=r"(a) : "l"(p));
    return a;
}
__device__ __forceinline__ void ldm4(uint32_t* r, uint32_t addr) {
    asm volatile("ldmatrix.sync.aligned.m8n8.x4.shared.b16 {%0,%1,%2,%3}, [%4];"
                 : "=r"(r[0]), "=r"(r[1]), "=r"(r[2]), "=r"(r[3]) : "r"(addr));
}
__device__ __forceinline__ void mma16816(float* c, const uint32_t* a, const uint32_t* b) {
    asm volatile("mma.sync.aligned.m16n8k16.row.col.f32.f16.f16.f32 "
                 "{%0,%1,%2,%3}, {%4,%5,%6,%7}, {%8,%9}, {%0,%1,%2,%3};"
                 : "+f"(c[0]), "+f"(c[1]), "+f"(c[2]), "+f"(c[3])
                 : "r"(a[0]), "r"(a[1]), "r"(a[2]), "r"(a[3]), "r"(b[0]), "r"(b[1]));
}
__device__ __forceinline__ void st128(uint32_t a, uint4 v) {
    asm volatile("st.shared.v4.b32 [%0], {%1,%2,%3,%4};"
                 :: "r"(a), "r"(v.x), "r"(v.y), "r"(v.z), "r"(v.w) : "memory");
}
__device__ __forceinline__ void cp16(uint32_t dst, const void* src, int szbytes) {
    asm volatile("cp.async.cg.shared.global [%0], [%1], 16, %2;"
                 :: "r"(dst), "l"(src), "r"(szbytes) : "memory");
}
#define CP_COMMIT() asm volatile("cp.async.commit_group;" ::: "memory")
__device__ __forceinline__ uint32_t packh2(__half a, __half b) {
    __half2 h = __halves2half2(a, b);
    return *reinterpret_cast<uint32_t*>(&h);
}
__device__ __forceinline__ void split8(float4 u, float4 v, uint4& hi, uint4& lo) {
    float f[8] = {u.x,u.y,u.z,u.w, v.x,v.y,v.z,v.w};
    __half h[8], l[8];
    #pragma unroll
    for (int i = 0; i < 8; i++) {
        h[i] = __float2half_rn(f[i]);
        l[i] = __float2half_rn(f[i] - __half2float(h[i]));
    }
    hi = make_uint4(packh2(h[0],h[1]), packh2(h[2],h[3]), packh2(h[4],h[5]), packh2(h[6],h[7]));
    lo = make_uint4(packh2(l[0],l[1]), packh2(l[2],l[3]), packh2(l[4],l[5]), packh2(l[6],l[7]));
}
// pack 8 floats to 8 fp16 (hi only; no residual)
__device__ __forceinline__ uint4 pack8h(float4 u, float4 v) {
    float f[8] = {u.x,u.y,u.z,u.w, v.x,v.y,v.z,v.w};
    __half h[8];
    #pragma unroll
    for (int i = 0; i < 8; i++) h[i] = __float2half_rn(f[i]);
    return make_uint4(packh2(h[0],h[1]), packh2(h[2],h[3]),
                      packh2(h[4],h[5]), packh2(h[6],h[7]));
}
// load 16 contiguous fp16 channels -> 8 float2
__device__ __forceinline__ void gath16(const __half* p, float2* f) {
    uint4 q0 = *(const uint4*)p;
    uint4 q1 = *(const uint4*)(p + 8);
    uint32_t u[8] = {q0.x,q0.y,q0.z,q0.w, q1.x,q1.y,q1.z,q1.w};
    #pragma unroll
    for (int i = 0; i < 8; i++) f[i] = __half22float2(*(const __half2*)&u[i]);
}

// ======= 3x3 conv implicit GEMM with HALO-STAGED A (R15, unchanged) =======
template<int N, int WN, int OUTK, bool RELU, int CPT>
__global__ void __launch_bounds__(128, 2)
mma_conv_halo(const __half* __restrict__ in0h, const __half* __restrict__ in1h,
              const __half* __restrict__ BT, const float* __restrict__ bias,
              float* __restrict__ outf, __half* __restrict__ outh,
              int S0, int S1, int C0CH, int OUT_CS)
{
    constexpr int WM = 4 / WN;
    constexpr int MT = 128 / WM;
    constexpr int NT = N / WN;
    constexpr int MF = MT / 16;
    constexpr int NF = NT / 8;
    constexpr int HROWS = 204;
    constexpr int ASTR  = 144;
    constexpr int ABUFH = HROWS * ASTR;
    constexpr int BBUF  = N * 128;
    constexpr int NCH   = CPT * 9;

    extern __shared__ __align__(16) char dsm[];
    const uint32_t smb = (smem_u32(dsm) + 127u) & ~127u;
    const uint32_t Bbase = smb + 2*ABUFH;

    const int t = threadIdx.x;
    const int w = t >> 5, lane = t & 31;
    const int wm = w % WM, wn = w / WM;
    const int xb = blockIdx.x * 32, yb = blockIdx.y * 4, b = blockIdx.z;

    float acc[MF][NF][4];
    #pragma unroll
    for (int i = 0; i < MF; i++)
        #pragma unroll
        for (int j = 0; j < NF; j++)
            #pragma unroll
            for (int r = 0; r < 4; r++) acc[i][j][r] = 0.f;

    int Lb[MF];
    #pragma unroll
    for (int mf = 0; mf < MF; mf++) {
        const int m = wm*MT + mf*16 + (lane & 15);
        Lb[mf] = ((m >> 5)*34 + (m & 31))*ASTR;
    }

    auto stageA = [&](int ci, int buf) {
        const uint32_t Ab = smb + (uint32_t)buf * ABUFH;
        #pragma unroll 4
        for (int e = t; e < HROWS*8; e += 128) {
            const int row = e >> 3, ch = e & 7;
            const int gy = yb + row/34 - 1;
            const int gx = xb + row%34 - 1;
            const bool ok = (gy >= 0 && gy < Hh && gx >= 0 && gx < Ww);
            const size_t pix = (size_t)b*HW + (size_t)(ok ? gy : 0)*Ww + (ok ? gx : 0);
            const __half* src = (ci < C0CH)
                ? in0h + (pix*S0 + ci)*64 + ch*8
                : in1h + (pix*S1 + (ci - C0CH))*64 + ch*8;
            cp16(Ab + (uint32_t)(row*ASTR + ch*16), src, ok ? 16 : 0);
        }
    };

    auto stageB = [&](int it) {
        const int kcW = (it % 9)*CPT + (it / 9);
        const __half* bsrc = BT + (size_t)kcW*N*64;
        const uint32_t bb = Bbase + (uint32_t)(it % 3)*BBUF;
        #pragma unroll
        for (int i = 0; i < N/16; i++)
            cp16(bb + (uint32_t)(t + i*128)*16, bsrc + (t + i*128)*8, 16);
    };

    auto compute = [&](int it) {
        const uint32_t Ab = smb + (uint32_t)((it/9) & 1) * ABUFH;
        const int tap = it % 9;
        const uint32_t Tof = (uint32_t)(((tap/3)*34 + (tap%3))*ASTR);
        const uint32_t Bb = Bbase + (uint32_t)(it % 3)*BBUF;
        #pragma unroll
        for (int ks = 0; ks < 2; ks++) {
            uint32_t ah[MF][4], al[MF][4];
            #pragma unroll
            for (int mf = 0; mf < MF; mf++) {
                const uint32_t ra = Ab + Tof + (uint32_t)Lb[mf]
                                  + (uint32_t)((ks*2 + (lane >> 4)) << 4);
                ldm4(ah[mf], ra);
                ldm4(al[mf], ra + 64);
            }
            #pragma unroll
            for (int nf2 = 0; nf2 < NF/2; nf2++) {
                uint32_t bh[4], bl[4];
                const int oc  = wn*NT + nf2*16 + (lane & 7) + ((lane >> 4) << 3);
                const int chb = ks*2 + ((lane >> 3) & 1);
                const uint32_t rb = Bb + oc*128;
                ldm4(bh, rb + (uint32_t)((chb ^ (oc&7)) << 4));
                ldm4(bl, rb + (uint32_t)(((chb+4) ^ (oc&7)) << 4));
                #pragma unroll
                for (int mf = 0; mf < MF; mf++) mma16816(acc[mf][2*nf2  ], ah[mf], bh+0);
                #pragma unroll
                for (int mf = 0; mf < MF; mf++) mma16816(acc[mf][2*nf2+1], ah[mf], bh+2);
                #pragma unroll
                for (int mf = 0; mf < MF; mf++) mma16816(acc[mf][2*nf2  ], ah[mf], bl+0);
                #pragma unroll
                for (int mf = 0; mf < MF; mf++) mma16816(acc[mf][2*nf2+1], ah[mf], bl+2);
                #pragma unroll
                for (int mf = 0; mf < MF; mf++) mma16816(acc[mf][2*nf2  ], al[mf], bh+0);
                #pragma unroll
                for (int mf = 0; mf < MF; mf++) mma16816(acc[mf][2*nf2+1], al[mf], bh+2);
            }
        }
    };

    stageA(0, 0);
    stageB(0);
    CP_COMMIT();
    stageB(1);
    CP_COMMIT();

    for (int it = 0; it < NCH; it++) {
        if (it + 1 < NCH) { asm volatile("cp.async.wait_group 1;" ::: "memory"); }
        else              { asm volatile("cp.async.wait_group 0;" ::: "memory"); }
        __syncthreads();
        compute(it);
        if (it + 2 < NCH) {
            stageB(it + 2);
            const int ci = it / 9;
            if ((it % 9) == 1 && ci + 1 < CPT) stageA(ci + 1, (ci + 1) & 1);
            CP_COMMIT();
        }
    }

    const int lrow = lane >> 2, lcol = (lane & 3) * 2;
    #pragma unroll
    for (int mf = 0; mf < MF; mf++) {
        #pragma unroll
        for (int nf = 0; nf < NF; nf++) {
            const int oc = wn*NT + nf*8 + lcol;
            float bx = 0.f, by = 0.f;
            if (bias != nullptr) { bx = __ldg(bias + oc); by = __ldg(bias + oc + 1); }
            #pragma unroll
            for (int rp = 0; rp < 2; rp++) {
                const int m = wm*MT + mf*16 + lrow + rp*8;
                const int y = yb + (m >> 5), x = xb + (m & 31);
                float c0 = acc[mf][nf][rp*2] + bx;
                float c1 = acc[mf][nf][rp*2+1] + by;
                if (RELU) { c0 = fmaxf(c0, 0.f); c1 = fmaxf(c1, 0.f); }
                const size_t pix = (size_t)b*HW + (size_t)y*Ww + x;
                if (OUTK == 0) {
                    *(float2*)(outf + pix*OUT_CS + oc) = make_float2(c0, c1);
                } else {
                    __half h0 = __float2half_rn(c0);
                    __half l0 = __float2half_rn(c0 - __half2float(h0));
                    __half h1 = __float2half_rn(c1);
                    __half l1 = __float2half_rn(c1 - __half2float(h1));
                    __half* dst = outh + (pix*(N/32) + (oc >> 5))*64 + (oc & 31);
                    *(__half2*)dst        = __halves2half2(h0, h1);
                    *(__half2*)(dst + 32) = __halves2half2(l0, l1);
                }
            }
        }
    }
}

// ======= fused deformable sampling + 1x1 contraction (K=576 -> 64), fp32 NCHW out =======
// 2-TERM split: samples stored hi-only (ah); MMA = ah*bh + ah*bl = ah x exact-B.
// Dropped al*B term is the fp16 residue of the SAMPLES (~2^-12.5 rel), amplification 1
// (downstream of offsets). A staging stores hi only; al fragments never loaded.
__global__ void __launch_bounds__(256)
deform_mma(const __half* __restrict__ hrh, const float* __restrict__ offp,
           const __half* __restrict__ BT, float* __restrict__ outf)
{
    constexpr int N = 64, NCH = 18;
    constexpr int MF = 2, NF = 4;          // WM=4 (MT=32), WN=2 (NT=32)
    constexpr int ABUF = 128 * 128;        // keep 128B row stride (hi at +0..63, lo region unused)
    constexpr int BBUF = N * 128;
    constexpr int BV = N / 32;

    extern __shared__ __align__(16) char dsm[];
    const uint32_t smb = (smem_u32(dsm) + 127u) & ~127u;
    const uint32_t Ab0 = smb, Ab1 = smb + ABUF;
    const uint32_t Bb0 = smb + 2*ABUF, Bb1 = smb + 2*ABUF + BBUF;

    const int t = threadIdx.x;
    const int w = t >> 5, lane = t & 31;
    const int wm = w % 4, wn = w / 4;
    const int xb = blockIdx.x * 32, yb = blockIdx.y * 4, b = blockIdx.z;

    float acc[MF][NF][4];
    #pragma unroll
    for (int i = 0; i < MF; i++)
        #pragma unroll
        for (int j = 0; j < NF; j++)
            #pragma unroll
            for (int r = 0; r < 4; r++) acc[i][j][r] = 0.f;

    const int px = t >> 1, half = t & 1;
    const int prow = px >> 5, pcol = px & 31;

    float4 avf[4];
    uint4  bv[BV];
    const __half *cp00 = nullptr, *cp01 = nullptr, *cp10 = nullptr, *cp11 = nullptr;
    float cw00 = 0.f, cw01 = 0.f, cw10 = 0.f, cw11 = 0.f;

    auto load_a = [&](int kc) {
        const int tap = kc >> 1;
        if ((kc & 1) == 0) {
            const int y = yb + prow, x = xb + pcol;
            const size_t pix = (size_t)b*HW + (size_t)y*Ww + x;
            const float dy = offp[pix*32 + 2*tap];
            const float dx = offp[pix*32 + 2*tap + 1];
            const float py  = (float)(y + tap/3 - 1) + dy;
            const float pxx = (float)(x + tap%3 - 1) + dx;
            const float y0f = floorf(py), x0f = floorf(pxx);
            const float wy = py - y0f, wx = pxx - x0f;
            const int yi = (int)y0f, xi = (int)x0f;
            const bool vy0 = (yi   >= 0) && (yi   <= Hh-1);
            const bool vy1 = (yi+1 >= 0) && (yi+1 <= Hh-1);
            const bool vx0 = (xi   >= 0) && (xi   <= Ww-1);
            const bool vx1 = (xi+1 >= 0) && (xi+1 <= Ww-1);
            const int yc0 = min(max(yi,   0), Hh-1);
            const int yc1 = min(max(yi+1, 0), Hh-1);
            const int xc0 = min(max(xi,   0), Ww-1);
            const int xc1 = min(max(xi+1, 0), Ww-1);
            cw00 = (1.f-wy)*(1.f-wx) * ((vy0 && vx0) ? 1.f : 0.f);
            cw01 = (1.f-wy)*wx       * ((vy0 && vx1) ? 1.f : 0.f);
            cw10 = wy*(1.f-wx)       * ((vy1 && vx0) ? 1.f : 0.f);
            cw11 = wy*wx             * ((vy1 && vx1) ? 1.f : 0.f);
            const __half* base = hrh + (size_t)b*HW*64;
            cp00 = base + ((size_t)yc0*Ww + xc0)*64;
            cp01 = base + ((size_t)yc0*Ww + xc1)*64;
            cp10 = base + ((size_t)yc1*Ww + xc0)*64;
            cp11 = base + ((size_t)yc1*Ww + xc1)*64;
        }
        const int cb = ((kc & 1) << 5) + half * 16;
        float2 f00[8], f01[8], f10[8], f11[8];
        gath16(cp00 + cb, f00);
        gath16(cp01 + cb, f01);
        gath16(cp10 + cb, f10);
        gath16(cp11 + cb, f11);
        #pragma unroll
        for (int i = 0; i < 8; i++) {
            const float vx = cw00*f00[i].x + cw01*f01[i].x + cw10*f10[i].x + cw11*f11[i].x;
            const float vy = cw00*f00[i].y + cw01*f01[i].y + cw10*f10[i].y + cw11*f11[i].y;
            if (i & 1) { avf[i>>1].z = vx; avf[i>>1].w = vy; }
            else       { avf[i>>1].x = vx; avf[i>>1].y = vy; }
        }
    };
    auto load_b = [&](int kc) {
        const uint4* src = (const uint4*)(BT + (size_t)kc*N*64);
        #pragma unroll
        for (int i = 0; i < BV; i++) bv[i] = src[t + i*256];
    };
    auto sts_ab = [&](uint32_t Ab, uint32_t Bb) {
        const uint32_t rowb = Ab + px*128;
        const uint32_t sw = px & 7;
        #pragma unroll
        for (int i = 0; i < 2; i++) {
            const int ch = half*2 + i;
            st128(rowb + (uint32_t)((ch ^ sw) << 4), pack8h(avf[2*i], avf[2*i+1]));
        }
        #pragma unroll
        for (int i = 0; i < BV; i++) st128(Bb + (t + i*256)*16, bv[i]);
    };
    auto compute = [&](uint32_t Ab, uint32_t Bb) {
        #pragma unroll
        for (int ks = 0; ks < 2; ks++) {
            uint32_t ah[MF][4];
            #pragma unroll
            for (int mf = 0; mf < MF; mf++) {
                const int row = wm*32 + mf*16 + (lane & 15);
                const int chh = ks*2 + (lane >> 4);
                const uint32_t rb = Ab + row*128;
                ldm4(ah[mf], rb + (uint32_t)((chh ^ (row&7)) << 4));
            }
            #pragma unroll
            for (int nf2 = 0; nf2 < NF/2; nf2++) {
                uint32_t bh[4], bl[4];
                const int oc  = wn*32 + nf2*16 + (lane & 7) + ((lane >> 4) << 3);
                const int chb = ks*2 + ((lane >> 3) & 1);
                const uint32_t rb = Bb + oc*128;
                ldm4(bh, rb + (uint32_t)((chb ^ (oc&7)) << 4));
                ldm4(bl, rb + (uint32_t)(((chb+4) ^ (oc&7)) << 4));
                #pragma unroll
                for (int mf = 0; mf < MF; mf++) mma16816(acc[mf][2*nf2  ], ah[mf], bh+0);
                #pragma unroll
                for (int mf = 0; mf < MF; mf++) mma16816(acc[mf][2*nf2+1], ah[mf], bh+2);
                #pragma unroll
                for (int mf = 0; mf < MF; mf++) mma16816(acc[mf][2*nf2  ], ah[mf], bl+0);
                #pragma unroll
                for (int mf = 0; mf < MF; mf++) mma16816(acc[mf][2*nf2+1], ah[mf], bl+2);
            }
        }
    };

    load_a(0); load_b(0);
    sts_ab(Ab0, Bb0);
    __syncthreads();

    for (int kc = 0; kc < NCH; kc++) {
        if (kc + 1 < NCH) { load_a(kc+1); load_b(kc+1); }
        compute((kc & 1) ? Ab1 : Ab0, (kc & 1) ? Bb1 : Bb0);
        if (kc + 1 < NCH) {
            sts_ab(((kc+1) & 1) ? Ab1 : Ab0, ((kc+1) & 1) ? Bb1 : Bb0);
            __syncthreads();
        }
    }

    const int lrow = lane >> 2, lcol = (lane & 3) * 2;
    #pragma unroll
    for (int mf = 0; mf < MF; mf++) {
        #pragma unroll
        for (int nf = 0; nf < NF; nf++) {
            const int oc = wn*32 + nf*8 + lcol;
            #pragma unroll
            for (int rp = 0; rp < 2; rp++) {
                const int m = wm*32 + mf*16 + lrow + rp*8;
                const int y = yb + (m >> 5), x = xb + (m & 31);
                const size_t p = (size_t)y*Ww + x;
                outf[((size_t)b*N + oc  )*HW + p] = acc[mf][nf][rp*2];
                outf[((size_t)b*N + oc+1)*HW + p] = acc[mf][nf][rp*2+1];
            }
        }
    }
}

// ---------------- NCHW fp32 -> split fp16 NHWC chunks, lr+hr in one launch ----------------
__global__ void to_nhwc_dual(const float* __restrict__ lr, const float* __restrict__ hr,
                             __half* __restrict__ lrs, __half* __restrict__ hrs,
                             __half* __restrict__ hrh)
{
    __shared__ float tl[32][33];
    const int ysel = blockIdx.y;
    const bool is_hr = (ysel >= 2);
    const float* src = is_hr ? hr : lr;
    __half* dsts = is_hr ? hrs : lrs;
    const int p0 = blockIdx.x*32, c0 = (ysel & 1)*32, b = blockIdx.z;
    const int lx = threadIdx.x & 31, ly = threadIdx.x >> 5;
    #pragma unroll
    for (int i = 0; i < 32; i += 8)
        tl[ly+i][lx] = src[((size_t)b*64 + c0 + ly + i)*HW + p0 + lx];
    __syncthreads();
    #pragma unroll
    for (int i = 0; i < 32; i += 8) {
        const int pix = p0 + ly + i, c = c0 + lx;
        const float v = tl[lx][ly+i];
        __half h = __float2half_rn(v);
        __half l = __float2half_rn(v - __half2float(h));
        __half* d = dsts + (((size_t)b*HW + pix)*2 + (c >> 5))*64 + (c & 31);
        d[0]  = h;
        d[32] = l;
        if (is_hr) hrh[((size_t)b*HW + pix)*64 + c] = h;
    }
}

// ---------------- weight reformat: split fp16 hi/lo + pre-swizzle smem image ----------------
__global__ void reformat_w_split(const float* __restrict__ w, __half* __restrict__ BT,
                                 int COUT, int NPAD, int CIN, int TOT)
{
    int i = blockIdx.x*blockDim.x + threadIdx.x;
    if (i >= TOT) return;
    int j  = i & 31;
    int oc = (i >> 5) % NPAD;
    int kc = i / (32 * NPAD);
    int kidx = kc*32 + j;
    int tap = kidx / CIN, cin = kidx % CIN;
    float v = (oc < COUT) ? w[((size_t)oc*CIN + cin)*9 + tap] : 0.f;
    __half h = __float2half_rn(v);
    __half l = __float2half_rn(v - __half2float(h));
    int sw = oc & 7;
    size_t rowb = ((size_t)kc*NPAD + oc) * 64;
    int ch = j >> 3, pos = j & 7;
    BT[rowb + (size_t)(((ch    ) ^ sw) << 3) + pos] = h;
    BT[rowb + (size_t)(((ch + 4) ^ sw) << 3) + pos] = l;
}

// ---------------- launch ----------------
extern "C" void kernel_launch(void* const* d_in, const int* in_sizes, int n_in,
                              void* d_out, int out_size)
{
    (void)in_sizes; (void)n_in; (void)out_size;
    const float* lr = (const float*)d_in[0];
    const float* hr = (const float*)d_in[1];
    const float* w1 = (const float*)d_in[2];
    const float* b1 = (const float*)d_in[3];
    const float* w2 = (const float*)d_in[4];
    const float* b2 = (const float*)d_in[5];
    const float* wo = (const float*)d_in[6];
    const float* wd = (const float*)d_in[7];
    float* out = (float*)d_out;

    __half *plrs, *phrs, *ph1s, *ph2s, *phrh, *pBT1, *pBT2, *pBTo, *pBTd;
    float *poff;
    cudaGetSymbolAddress((void**)&plrs, g_lrs);
    cudaGetSymbolAddress((void**)&phrs, g_hrs);
    cudaGetSymbolAddress((void**)&ph1s, g_h1s);
    cudaGetSymbolAddress((void**)&ph2s, g_h2s);
    cudaGetSymbolAddress((void**)&phrh, g_hrh);
    cudaGetSymbolAddress((void**)&poff, g_off);
    cudaGetSymbolAddress((void**)&pBT1, g_BT1);
    cudaGetSymbolAddress((void**)&pBT2, g_BT2);
    cudaGetSymbolAddress((void**)&pBTo, g_BTo);
    cudaGetSymbolAddress((void**)&pBTd, g_BTd);

    const int SZ128 = 2*29376 + 3*16384 + 128;   // 108160
    const int SZ32  = 2*29376 + 3*4096  + 128;   //  71168
    const int SZD   = 2*16384 + 2*64*128;        //  49152
    cudaFuncSetAttribute(mma_conv_halo<128,2,1,true ,4>,
                         cudaFuncAttributeMaxDynamicSharedMemorySize, SZ128);
    cudaFuncSetAttribute(mma_conv_halo<32 ,1,0,false,4>,
                         cudaFuncAttributeMaxDynamicSharedMemorySize, SZ32);
    cudaFuncSetAttribute(deform_mma,
                         cudaFuncAttributeMaxDynamicSharedMemorySize, SZD);

    // launch order: conv1 at index 3 (ncu profiles launch index 3)
    reformat_w_split<<<(36*128*32+255)/256, 256>>>(w1, pBT1, 128, 128, 128, 36*128*32); // 0
    to_nhwc_dual<<<dim3(800,4,Bn), 256>>>(lr, hr, plrs, phrs, phrh);                    // 1
    reformat_w_split<<<(36*128*32+255)/256, 256>>>(w2, pBT2, 128, 128, 128, 36*128*32); // 2

    // conv1: concat(lr|hr)(128) -> 128, relu, split-fp16 out   [launch 3: PROFILED]
    mma_conv_halo<128,2,1,true ,4><<<dim3(5,40,Bn), 128, SZ128>>>(
        plrs, phrs, pBT1, b1, nullptr, ph1s, 2, 2, 2, 0);

    reformat_w_split<<<(36*32*32 +255)/256, 256>>>(wo, pBTo, 18,  32,  128, 36*32*32);  // 4
    reformat_w_split<<<(18*64*32 +255)/256, 256>>>(wd, pBTd, 64,  64,  64,  18*64*32);  // 5

    // conv2: 128 -> 128, relu, split-fp16 out
    mma_conv_halo<128,2,1,true ,4><<<dim3(5,40,Bn), 128, SZ128>>>(
        ph1s, ph1s, pBT2, b2, nullptr, ph2s, 4, 4, 4, 0);
    // offset conv: 128 -> 18 (pad 32), fp32 NHWC out (3-term: offset-critical)
    mma_conv_halo<32 ,1,0,false,4><<<dim3(5,40,Bn), 128, SZ32 >>>(
        ph2s, ph2s, pBTo, nullptr, poff, nullptr, 4, 4, 4, 32);
    // fused deformable sampling + contraction: K=576 -> 64, fp32 NCHW out (2-term)
    deform_mma<<<dim3(5,40,Bn), 256, SZD>>>(phrh, poff, pBTd, out);
}

// round 17
// speedup vs baseline: 2.0113x; 1.0159x over previous
#include <cuda_runtime.h>
#include <cuda_fp16.h>
#include <cstdint>

#define Hh 160
#define Ww 160
#define Bn 4
#define HW (Hh*Ww)

// ---------------- scratch (device globals; no allocation allowed) ----------------
// split-fp16 activations: [pix][chunk][hi 32 halfs | lo 32 halfs]  (64 halfs per chunk)
__device__ __align__(16) __half g_lrs[(size_t)Bn*HW*2*64];   // lr, 2 chunks (64ch)
__device__ __align__(16) __half g_hrs[(size_t)Bn*HW*2*64];   // hr, 2 chunks
__device__ __align__(16) __half g_h1s[(size_t)Bn*HW*4*64];   // conv1 out, 4 chunks (128ch)
__device__ __align__(16) __half g_h2s[(size_t)Bn*HW*4*64];   // conv2 out, 4 chunks
__device__ __align__(16) __half g_hrh[(size_t)Bn*HW*64];     // hr NHWC plain fp16 (deform gather)
__device__ float g_off[(size_t)Bn*HW*32];                    // offsets NHWC (18 used, pad 32)
// weights pre-split fp16 hi/lo, pre-swizzled smem image: [kc][oc][128 bytes]
__device__ __align__(16) __half g_BT1[36*128*64];
__device__ __align__(16) __half g_BT2[36*128*64];
__device__ __align__(16) __half g_BTo[36*32*64];
__device__ __align__(16) __half g_BTd[18*64*64];

// ---------------- helpers ----------------
__device__ __forceinline__ uint32_t smem_u32(const void* p) {
    uint32_t a;
    asm("{ .reg .u64 t; cvta.to.shared.u64 t, %1; cvt.u32.u64 %0, t; }" : "=r"(a) : "l"(p));
    return a;
}
__device__ __forceinline__ void ldm4(uint32_t* r, uint32_t addr) {
    asm volatile("ldmatrix.sync.aligned.m8n8.x4.shared.b16 {%0,%1,%2,%3}, [%4];"
                 : "=r"(r[0]), "=r"(r[1]), "=r"(r[2]), "=r"(r[3]) : "r"(addr));
}
__device__ __forceinline__ void mma16816(float* c, const uint32_t* a, const uint32_t* b) {
    asm volatile("mma.sync.aligned.m16n8k16.row.col.f32.f16.f16.f32 "
                 "{%0,%1,%2,%3}, {%4,%5,%6,%7}, {%8,%9}, {%0,%1,%2,%3};"
                 : "+f"(c[0]), "+f"(c[1]), "+f"(c[2]), "+f"(c[3])
                 : "r"(a[0]), "r"(a[1]), "r"(a[2]), "r"(a[3]), "r"(b[0]), "r"(b[1]));
}
__device__ __forceinline__ void st128(uint32_t a, uint4 v) {
    asm volatile("st.shared.v4.b32 [%0], {%1,%2,%3,%4};"
                 :: "r"(a), "r"(v.x), "r"(v.y), "r"(v.z), "r"(v.w) : "memory");
}
__device__ __forceinline__ void cp16(uint32_t dst, const void* src, int szbytes) {
    asm volatile("cp.async.cg.shared.global [%0], [%1], 16, %2;"
                 :: "r"(dst), "l"(src), "r"(szbytes) : "memory");
}
#define CP_COMMIT() asm volatile("cp.async.commit_group;" ::: "memory")
__device__ __forceinline__ uint32_t packh2(__half a, __half b) {
    __half2 h = __halves2half2(a, b);
    return *reinterpret_cast<uint32_t*>(&h);
}
__device__ __forceinline__ void split8(float4 u, float4 v, uint4& hi, uint4& lo) {
    float f[8] = {u.x,u.y,u.z,u.w, v.x,v.y,v.z,v.w};
    __half h[8], l[8];
    #pragma unroll
    for (int i = 0; i < 8; i++) {
        h[i] = __float2half_rn(f[i]);
        l[i] = __float2half_rn(f[i] - __half2float(h[i]));
    }
    hi = make_uint4(packh2(h[0],h[1]), packh2(h[2],h[3]), packh2(h[4],h[5]), packh2(h[6],h[7]));
    lo = make_uint4(packh2(l[0],l[1]), packh2(l[2],l[3]), packh2(l[4],l[5]), packh2(l[6],l[7]));
}

// ======= 3x3 conv implicit GEMM with HALO-STAGED A (R15/R16, unchanged) =======
template<int N, int WN, int OUTK, bool RELU, int CPT>
__global__ void __launch_bounds__(128, 2)
mma_conv_halo(const __half* __restrict__ in0h, const __half* __restrict__ in1h,
              const __half* __restrict__ BT, const float* __restrict__ bias,
              float* __restrict__ outf, __half* __restrict__ outh,
              int S0, int S1, int C0CH, int OUT_CS)
{
    constexpr int WM = 4 / WN;
    constexpr int MT = 128 / WM;
    constexpr int NT = N / WN;
    constexpr int MF = MT / 16;
    constexpr int NF = NT / 8;
    constexpr int HROWS = 204;
    constexpr int ASTR  = 144;
    constexpr int ABUFH = HROWS * ASTR;
    constexpr int BBUF  = N * 128;
    constexpr int NCH   = CPT * 9;

    extern __shared__ __align__(16) char dsm[];
    const uint32_t smb = (smem_u32(dsm) + 127u) & ~127u;
    const uint32_t Bbase = smb + 2*ABUFH;

    const int t = threadIdx.x;
    const int w = t >> 5, lane = t & 31;
    const int wm = w % WM, wn = w / WM;
    const int xb = blockIdx.x * 32, yb = blockIdx.y * 4, b = blockIdx.z;

    float acc[MF][NF][4];
    #pragma unroll
    for (int i = 0; i < MF; i++)
        #pragma unroll
        for (int j = 0; j < NF; j++)
            #pragma unroll
            for (int r = 0; r < 4; r++) acc[i][j][r] = 0.f;

    int Lb[MF];
    #pragma unroll
    for (int mf = 0; mf < MF; mf++) {
        const int m = wm*MT + mf*16 + (lane & 15);
        Lb[mf] = ((m >> 5)*34 + (m & 31))*ASTR;
    }

    auto stageA = [&](int ci, int buf) {
        const uint32_t Ab = smb + (uint32_t)buf * ABUFH;
        #pragma unroll 4
        for (int e = t; e < HROWS*8; e += 128) {
            const int row = e >> 3, ch = e & 7;
            const int gy = yb + row/34 - 1;
            const int gx = xb + row%34 - 1;
            const bool ok = (gy >= 0 && gy < Hh && gx >= 0 && gx < Ww);
            const size_t pix = (size_t)b*HW + (size_t)(ok ? gy : 0)*Ww + (ok ? gx : 0);
            const __half* src = (ci < C0CH)
                ? in0h + (pix*S0 + ci)*64 + ch*8
                : in1h + (pix*S1 + (ci - C0CH))*64 + ch*8;
            cp16(Ab + (uint32_t)(row*ASTR + ch*16), src, ok ? 16 : 0);
        }
    };

    auto stageB = [&](int it) {
        const int kcW = (it % 9)*CPT + (it / 9);
        const __half* bsrc = BT + (size_t)kcW*N*64;
        const uint32_t bb = Bbase + (uint32_t)(it % 3)*BBUF;
        #pragma unroll
        for (int i = 0; i < N/16; i++)
            cp16(bb + (uint32_t)(t + i*128)*16, bsrc + (t + i*128)*8, 16);
    };

    auto compute = [&](int it) {
        const uint32_t Ab = smb + (uint32_t)((it/9) & 1) * ABUFH;
        const int tap = it % 9;
        const uint32_t Tof = (uint32_t)(((tap/3)*34 + (tap%3))*ASTR);
        const uint32_t Bb = Bbase + (uint32_t)(it % 3)*BBUF;
        #pragma unroll
        for (int ks = 0; ks < 2; ks++) {
            uint32_t ah[MF][4], al[MF][4];
            #pragma unroll
            for (int mf = 0; mf < MF; mf++) {
                const uint32_t ra = Ab + Tof + (uint32_t)Lb[mf]
                                  + (uint32_t)((ks*2 + (lane >> 4)) << 4);
                ldm4(ah[mf], ra);
                ldm4(al[mf], ra + 64);
            }
            #pragma unroll
            for (int nf2 = 0; nf2 < NF/2; nf2++) {
                uint32_t bh[4], bl[4];
                const int oc  = wn*NT + nf2*16 + (lane & 7) + ((lane >> 4) << 3);
                const int chb = ks*2 + ((lane >> 3) & 1);
                const uint32_t rb = Bb + oc*128;
                ldm4(bh, rb + (uint32_t)((chb ^ (oc&7)) << 4));
                ldm4(bl, rb + (uint32_t)(((chb+4) ^ (oc&7)) << 4));
                #pragma unroll
                for (int mf = 0; mf < MF; mf++) mma16816(acc[mf][2*nf2  ], ah[mf], bh+0);
                #pragma unroll
                for (int mf = 0; mf < MF; mf++) mma16816(acc[mf][2*nf2+1], ah[mf], bh+2);
                #pragma unroll
                for (int mf = 0; mf < MF; mf++) mma16816(acc[mf][2*nf2  ], ah[mf], bl+0);
                #pragma unroll
                for (int mf = 0; mf < MF; mf++) mma16816(acc[mf][2*nf2+1], ah[mf], bl+2);
                #pragma unroll
                for (int mf = 0; mf < MF; mf++) mma16816(acc[mf][2*nf2  ], al[mf], bh+0);
                #pragma unroll
                for (int mf = 0; mf < MF; mf++) mma16816(acc[mf][2*nf2+1], al[mf], bh+2);
            }
        }
    };

    stageA(0, 0);
    stageB(0);
    CP_COMMIT();
    stageB(1);
    CP_COMMIT();

    for (int it = 0; it < NCH; it++) {
        if (it + 1 < NCH) { asm volatile("cp.async.wait_group 1;" ::: "memory"); }
        else              { asm volatile("cp.async.wait_group 0;" ::: "memory"); }
        __syncthreads();
        compute(it);
        if (it + 2 < NCH) {
            stageB(it + 2);
            const int ci = it / 9;
            if ((it % 9) == 1 && ci + 1 < CPT) stageA(ci + 1, (ci + 1) & 1);
            CP_COMMIT();
        }
    }

    const int lrow = lane >> 2, lcol = (lane & 3) * 2;
    #pragma unroll
    for (int mf = 0; mf < MF; mf++) {
        #pragma unroll
        for (int nf = 0; nf < NF; nf++) {
            const int oc = wn*NT + nf*8 + lcol;
            float bx = 0.f, by = 0.f;
            if (bias != nullptr) { bx = __ldg(bias + oc); by = __ldg(bias + oc + 1); }
            #pragma unroll
            for (int rp = 0; rp < 2; rp++) {
                const int m = wm*MT + mf*16 + lrow + rp*8;
                const int y = yb + (m >> 5), x = xb + (m & 31);
                float c0 = acc[mf][nf][rp*2] + bx;
                float c1 = acc[mf][nf][rp*2+1] + by;
                if (RELU) { c0 = fmaxf(c0, 0.f); c1 = fmaxf(c1, 0.f); }
                const size_t pix = (size_t)b*HW + (size_t)y*Ww + x;
                if (OUTK == 0) {
                    *(float2*)(outf + pix*OUT_CS + oc) = make_float2(c0, c1);
                } else {
                    __half h0 = __float2half_rn(c0);
                    __half l0 = __float2half_rn(c0 - __half2float(h0));
                    __half h1 = __float2half_rn(c1);
                    __half l1 = __float2half_rn(c1 - __half2float(h1));
                    __half* dst = outh + (pix*(N/32) + (oc >> 5))*64 + (oc & 31);
                    *(__half2*)dst        = __halves2half2(h0, h1);
                    *(__half2*)(dst + 32) = __halves2half2(l0, l1);
                }
            }
        }
    }
}

// ======= fused deformable sampling + 1x1 contraction (K=576 -> 64), fp32 NCHW out =======
// COALESCED GATHER: lane = (4-pixel subgroup sp=lane>>3, 16B slot j=lane&7); each LDG.128
// covers 4 contiguous 128B corner rows => 4 L1 wavefronts (was ~16). Whole 64-ch tap staged
// per iteration (9 barriers, was 18). B via cp.async, 3 tap-buffers. Arithmetic identical
// to R16 (fp32 bilinear, hi-only pack, 2-term MMA, same k order) => bit-identical output.
__global__ void __launch_bounds__(256)
deform_mma(const __half* __restrict__ hrh, const float* __restrict__ offp,
           const __half* __restrict__ BT, float* __restrict__ outf)
{
    constexpr int N = 64;
    constexpr int MF = 2, NF = 4;          // WM=4 (MT=32), WN=2 (NT=32)
    constexpr int ABUF = 128 * 128;        // 16KB: 128 px rows x 128B (64 ch fp16)
    constexpr int BBUF = 2 * N * 128;      // 16KB: both kchunks of one tap

    extern __shared__ __align__(16) char dsm[];
    const uint32_t smb = (smem_u32(dsm) + 127u) & ~127u;
    const uint32_t Bbase = smb + 2*ABUF;

    const int t = threadIdx.x;
    const int w = t >> 5, lane = t & 31;
    const int wm = w % 4, wn = w / 4;
    const int sp = (lane >> 3) & 3, j = lane & 7;
    const int wpx = w * 16;                // 16 pixels per warp for staging
    const int xb = blockIdx.x * 32, yb = blockIdx.y * 4, b = blockIdx.z;

    float acc[MF][NF][4];
    #pragma unroll
    for (int i = 0; i < MF; i++)
        #pragma unroll
        for (int jj = 0; jj < NF; jj++)
            #pragma unroll
            for (int r = 0; r < 4; r++) acc[i][jj][r] = 0.f;

    uint4 outv[4];                          // staged 16B per pixel-group

    auto load_tap = [&](int tap) {
        const int ky = tap/3 - 1, kx = tap%3 - 1;
        #pragma unroll
        for (int pg = 0; pg < 4; pg++) {
            const int p = wpx + pg*4 + sp;
            const int y = yb + (p >> 5), x = xb + (p & 31);
            const size_t pix = (size_t)b*HW + (size_t)y*Ww + x;
            const float2 dxy = *(const float2*)(offp + pix*32 + 2*tap);
            const float py  = (float)(y + ky) + dxy.x;
            const float pxx = (float)(x + kx) + dxy.y;
            const float y0f = floorf(py), x0f = floorf(pxx);
            const float wy = py - y0f, wx = pxx - x0f;
            const int yi = (int)y0f, xi = (int)x0f;
            const bool vy0 = (yi   >= 0) && (yi   <= Hh-1);
            const bool vy1 = (yi+1 >= 0) && (yi+1 <= Hh-1);
            const bool vx0 = (xi   >= 0) && (xi   <= Ww-1);
            const bool vx1 = (xi+1 >= 0) && (xi+1 <= Ww-1);
            const int yc0 = min(max(yi,   0), Hh-1);
            const int yc1 = min(max(yi+1, 0), Hh-1);
            const int xc0 = min(max(xi,   0), Ww-1);
            const int xc1 = min(max(xi+1, 0), Ww-1);
            const float w00 = (1.f-wy)*(1.f-wx) * ((vy0 && vx0) ? 1.f : 0.f);
            const float w01 = (1.f-wy)*wx       * ((vy0 && vx1) ? 1.f : 0.f);
            const float w10 = wy*(1.f-wx)       * ((vy1 && vx0) ? 1.f : 0.f);
            const float w11 = wy*wx             * ((vy1 && vx1) ? 1.f : 0.f);
            const __half* base = hrh + (size_t)b*HW*64 + j*8;
            const uint4 q00 = *(const uint4*)(base + ((size_t)yc0*Ww + xc0)*64);
            const uint4 q01 = *(const uint4*)(base + ((size_t)yc0*Ww + xc1)*64);
            const uint4 q10 = *(const uint4*)(base + ((size_t)yc1*Ww + xc0)*64);
            const uint4 q11 = *(const uint4*)(base + ((size_t)yc1*Ww + xc1)*64);
            const uint32_t a00[4] = {q00.x,q00.y,q00.z,q00.w};
            const uint32_t a01[4] = {q01.x,q01.y,q01.z,q01.w};
            const uint32_t a10[4] = {q10.x,q10.y,q10.z,q10.w};
            const uint32_t a11[4] = {q11.x,q11.y,q11.z,q11.w};
            uint32_t o[4];
            #pragma unroll
            for (int i = 0; i < 4; i++) {
                const float2 f00 = __half22float2(*(const __half2*)&a00[i]);
                const float2 f01 = __half22float2(*(const __half2*)&a01[i]);
                const float2 f10 = __half22float2(*(const __half2*)&a10[i]);
                const float2 f11 = __half22float2(*(const __half2*)&a11[i]);
                const float vx0f = w00*f00.x + w01*f01.x + w10*f10.x + w11*f11.x;
                const float vy0f = w00*f00.y + w01*f01.y + w10*f10.y + w11*f11.y;
                o[i] = packh2(__float2half_rn(vx0f), __float2half_rn(vy0f));
            }
            outv[pg] = make_uint4(o[0], o[1], o[2], o[3]);
        }
    };
    auto sts_tap = [&](int buf) {
        const uint32_t Ab = smb + (uint32_t)buf * ABUF;
        #pragma unroll
        for (int pg = 0; pg < 4; pg++) {
            const int p = wpx + pg*4 + sp;
            st128(Ab + (uint32_t)(p*128 + ((j ^ (p & 7)) << 4)), outv[pg]);
        }
    };
    auto stageB = [&](int tap) {
        const __half* bsrc = BT + (size_t)(2*tap)*N*64;   // both kchunks contiguous
        const uint32_t bb = Bbase + (uint32_t)(tap % 3)*BBUF;
        #pragma unroll
        for (int i = 0; i < 4; i++)
            cp16(bb + (uint32_t)(t + i*256)*16, bsrc + (t + i*256)*8, 16);
        CP_COMMIT();
    };
    auto compute = [&](int tap) {
        const uint32_t Ab = smb + (uint32_t)(tap & 1) * ABUF;
        #pragma unroll
        for (int kc2 = 0; kc2 < 2; kc2++) {
            const uint32_t Bb = Bbase + (uint32_t)(tap % 3)*BBUF + (uint32_t)kc2*(N*128);
            #pragma unroll
            for (int ks = 0; ks < 2; ks++) {
                uint32_t ah[MF][4];
                #pragma unroll
                for (int mf = 0; mf < MF; mf++) {
                    const int row = wm*32 + mf*16 + (lane & 15);
                    const int chh = kc2*4 + ks*2 + (lane >> 4);
                    ldm4(ah[mf], Ab + (uint32_t)(row*128 + ((chh ^ (row&7)) << 4)));
                }
                #pragma unroll
                for (int nf2 = 0; nf2 < NF/2; nf2++) {
                    uint32_t bh[4], bl[4];
                    const int oc  = wn*32 + nf2*16 + (lane & 7) + ((lane >> 4) << 3);
                    const int chb = ks*2 + ((lane >> 3) & 1);
                    const uint32_t rb = Bb + oc*128;
                    ldm4(bh, rb + (uint32_t)((chb ^ (oc&7)) << 4));
                    ldm4(bl, rb + (uint32_t)(((chb+4) ^ (oc&7)) << 4));
                    #pragma unroll
                    for (int mf = 0; mf < MF; mf++) mma16816(acc[mf][2*nf2  ], ah[mf], bh+0);
                    #pragma unroll
                    for (int mf = 0; mf < MF; mf++) mma16816(acc[mf][2*nf2+1], ah[mf], bh+2);
                    #pragma unroll
                    for (int mf = 0; mf < MF; mf++) mma16816(acc[mf][2*nf2  ], ah[mf], bl+0);
                    #pragma unroll
                    for (int mf = 0; mf < MF; mf++) mma16816(acc[mf][2*nf2+1], ah[mf], bl+2);
                }
            }
        }
    };

    stageB(0);
    load_tap(0);
    sts_tap(0);
    stageB(1);
    __syncthreads();

    for (int tap = 0; tap < 9; tap++) {
        if (tap + 1 < 9) load_tap(tap + 1);
        if (tap + 1 < 9) { asm volatile("cp.async.wait_group 1;" ::: "memory"); }
        else             { asm volatile("cp.async.wait_group 0;" ::: "memory"); }
        compute(tap);
        if (tap + 1 < 9) {
            sts_tap((tap + 1) & 1);
            if (tap + 2 < 9) stageB(tap + 2);
            __syncthreads();
        }
    }

    const int lrow = lane >> 2, lcol = (lane & 3) * 2;
    #pragma unroll
    for (int mf = 0; mf < MF; mf++) {
        #pragma unroll
        for (int nf = 0; nf < NF; nf++) {
            const int oc = wn*32 + nf*8 + lcol;
            #pragma unroll
            for (int rp = 0; rp < 2; rp++) {
                const int m = wm*32 + mf*16 + lrow + rp*8;
                const int y = yb + (m >> 5), x = xb + (m & 31);
                const size_t p = (size_t)y*Ww + x;
                outf[((size_t)b*N + oc  )*HW + p] = acc[mf][nf][rp*2];
                outf[((size_t)b*N + oc+1)*HW + p] = acc[mf][nf][rp*2+1];
            }
        }
    }
}

// ---------------- NCHW fp32 -> split fp16 NHWC chunks, lr+hr in one launch ----------------
__global__ void to_nhwc_dual(const float* __restrict__ lr, const float* __restrict__ hr,
                             __half* __restrict__ lrs, __half* __restrict__ hrs,
                             __half* __restrict__ hrh)
{
    __shared__ float tl[32][33];
    const int ysel = blockIdx.y;
    const bool is_hr = (ysel >= 2);
    const float* src = is_hr ? hr : lr;
    __half* dsts = is_hr ? hrs : lrs;
    const int p0 = blockIdx.x*32, c0 = (ysel & 1)*32, b = blockIdx.z;
    const int lx = threadIdx.x & 31, ly = threadIdx.x >> 5;
    #pragma unroll
    for (int i = 0; i < 32; i += 8)
        tl[ly+i][lx] = src[((size_t)b*64 + c0 + ly + i)*HW + p0 + lx];
    __syncthreads();
    #pragma unroll
    for (int i = 0; i < 32; i += 8) {
        const int pix = p0 + ly + i, c = c0 + lx;
        const float v = tl[lx][ly+i];
        __half h = __float2half_rn(v);
        __half l = __float2half_rn(v - __half2float(h));
        __half* d = dsts + (((size_t)b*HW + pix)*2 + (c >> 5))*64 + (c & 31);
        d[0]  = h;
        d[32] = l;
        if (is_hr) hrh[((size_t)b*HW + pix)*64 + c] = h;
    }
}

// ---------------- weight reformat: split fp16 hi/lo + pre-swizzle smem image ----------------
__global__ void reformat_w_split(const float* __restrict__ w, __half* __restrict__ BT,
                                 int COUT, int NPAD, int CIN, int TOT)
{
    int i = blockIdx.x*blockDim.x + threadIdx.x;
    if (i >= TOT) return;
    int j  = i & 31;
    int oc = (i >> 5) % NPAD;
    int kc = i / (32 * NPAD);
    int kidx = kc*32 + j;
    int tap = kidx / CIN, cin = kidx % CIN;
    float v = (oc < COUT) ? w[((size_t)oc*CIN + cin)*9 + tap] : 0.f;
    __half h = __float2half_rn(v);
    __half l = __float2half_rn(v - __half2float(h));
    int sw = oc & 7;
    size_t rowb = ((size_t)kc*NPAD + oc) * 64;
    int ch = j >> 3, pos = j & 7;
    BT[rowb + (size_t)(((ch    ) ^ sw) << 3) + pos] = h;
    BT[rowb + (size_t)(((ch + 4) ^ sw) << 3) + pos] = l;
}

// ---------------- launch ----------------
extern "C" void kernel_launch(void* const* d_in, const int* in_sizes, int n_in,
                              void* d_out, int out_size)
{
    (void)in_sizes; (void)n_in; (void)out_size;
    const float* lr = (const float*)d_in[0];
    const float* hr = (const float*)d_in[1];
    const float* w1 = (const float*)d_in[2];
    const float* b1 = (const float*)d_in[3];
    const float* w2 = (const float*)d_in[4];
    const float* b2 = (const float*)d_in[5];
    const float* wo = (const float*)d_in[6];
    const float* wd = (const float*)d_in[7];
    float* out = (float*)d_out;

    __half *plrs, *phrs, *ph1s, *ph2s, *phrh, *pBT1, *pBT2, *pBTo, *pBTd;
    float *poff;
    cudaGetSymbolAddress((void**)&plrs, g_lrs);
    cudaGetSymbolAddress((void**)&phrs, g_hrs);
    cudaGetSymbolAddress((void**)&ph1s, g_h1s);
    cudaGetSymbolAddress((void**)&ph2s, g_h2s);
    cudaGetSymbolAddress((void**)&phrh, g_hrh);
    cudaGetSymbolAddress((void**)&poff, g_off);
    cudaGetSymbolAddress((void**)&pBT1, g_BT1);
    cudaGetSymbolAddress((void**)&pBT2, g_BT2);
    cudaGetSymbolAddress((void**)&pBTo, g_BTo);
    cudaGetSymbolAddress((void**)&pBTd, g_BTd);

    const int SZ128 = 2*29376 + 3*16384 + 128;   // 108160
    const int SZ32  = 2*29376 + 3*4096  + 128;   //  71168
    const int SZD   = 2*16384 + 3*16384 + 128;   //  82048
    cudaFuncSetAttribute(mma_conv_halo<128,2,1,true ,4>,
                         cudaFuncAttributeMaxDynamicSharedMemorySize, SZ128);
    cudaFuncSetAttribute(mma_conv_halo<32 ,1,0,false,4>,
                         cudaFuncAttributeMaxDynamicSharedMemorySize, SZ32);
    cudaFuncSetAttribute(deform_mma,
                         cudaFuncAttributeMaxDynamicSharedMemorySize, SZD);

    // launch order: conv1 at index 3 (ncu profiles launch index 3)
    reformat_w_split<<<(36*128*32+255)/256, 256>>>(w1, pBT1, 128, 128, 128, 36*128*32); // 0
    to_nhwc_dual<<<dim3(800,4,Bn), 256>>>(lr, hr, plrs, phrs, phrh);                    // 1
    reformat_w_split<<<(36*128*32+255)/256, 256>>>(w2, pBT2, 128, 128, 128, 36*128*32); // 2

    // conv1: concat(lr|hr)(128) -> 128, relu, split-fp16 out   [launch 3: PROFILED]
    mma_conv_halo<128,2,1,true ,4><<<dim3(5,40,Bn), 128, SZ128>>>(
        plrs, phrs, pBT1, b1, nullptr, ph1s, 2, 2, 2, 0);

    reformat_w_split<<<(36*32*32 +255)/256, 256>>>(wo, pBTo, 18,  32,  128, 36*32*32);  // 4
    reformat_w_split<<<(18*64*32 +255)/256, 256>>>(wd, pBTd, 64,  64,  64,  18*64*32);  // 5

    // conv2: 128 -> 128, relu, split-fp16 out
    mma_conv_halo<128,2,1,true ,4><<<dim3(5,40,Bn), 128, SZ128>>>(
        ph1s, ph1s, pBT2, b2, nullptr, ph2s, 4, 4, 4, 0);
    // offset conv: 128 -> 18 (pad 32), fp32 NHWC out (3-term: offset-critical)
    mma_conv_halo<32 ,1,0,false,4><<<dim3(5,40,Bn), 128, SZ32 >>>(
        ph2s, ph2s, pBTo, nullptr, poff, nullptr, 4, 4, 4, 32);
    // fused deformable sampling + contraction: K=576 -> 64, fp32 NCHW out (2-term, coalesced gather)
    deform_mma<<<dim3(5,40,Bn), 256, SZD>>>(phrh, poff, pBTd, out);
}